// round 5
// baseline (speedup 1.0000x reference)
#include <cuda_runtime.h>
#include <cuda_bf16.h>
#include <math.h>

#define BATCH 4
#define SEQ   2048
#define DIM   1024
#define NH    16
#define HD    64
#define M_TOTAL (BATCH*SEQ)

// Scratch (device globals; no runtime allocation allowed)
__device__ float g_q[M_TOTAL*DIM];
__device__ float g_k[M_TOTAL*DIM];
__device__ float g_v[M_TOTAL*DIM];
__device__ float g_attn[M_TOTAL*DIM];
// Full scores buffer: [B*NH, SEQ, SEQ] = 268,435,456 floats = 1 GiB
__device__ float g_s[(size_t)BATCH*NH*SEQ*SEQ];

// ============================================================================
// Boring SGEMM:  C[M,1024] = A[M,1024] @ W[1024,1024]^T
// 32x32 tile, one output per thread, padded smem, scalar FMA only.
// ============================================================================
__global__ void gemm32_kernel(const float* __restrict__ A,
                              const float* __restrict__ W,
                              float* __restrict__ C)
{
    __shared__ float As[32][33];
    __shared__ float Ws[32][33];

    const int tx = threadIdx.x;       // 0..31
    const int ty = threadIdx.y;       // 0..31
    const int m  = blockIdx.y * 32 + ty;
    const int n0 = blockIdx.x * 32;

    float acc = 0.f;
    for (int k0 = 0; k0 < DIM; k0 += 32) {
        As[ty][tx] = A[(size_t)m * DIM + k0 + tx];               // A[m][k0+tx]
        Ws[ty][tx] = W[(size_t)(n0 + ty) * DIM + k0 + tx];       // W[n0+ty][k0+tx]
        __syncthreads();
        #pragma unroll 8
        for (int kk = 0; kk < 32; kk++)
            acc = fmaf(As[ty][kk], Ws[tx][kk], acc);             // sum_k A[m][k]*W[n0+tx][k]
        __syncthreads();
    }
    C[(size_t)m * DIM + n0 + tx] = acc;
}

// ============================================================================
// RoPE in place on Q and K ([B,L,D] layout). Double-precision trig.
// q'[j]    = q[j]*cos - q[j+32]*sin   (j in [0,32) within each head)
// q'[j+32] = q[j+32]*cos + q[j]*sin,  angle = l * 10000^(-j/32)
// ============================================================================
__global__ void rope_kernel(float* __restrict__ q, float* __restrict__ k)
{
    int idx = blockIdx.x * blockDim.x + threadIdx.x;   // over M_TOTAL*NH*32
    int j  = idx & 31;
    int h  = (idx >> 5) & (NH - 1);
    int ml = idx >> 9;                                  // b*SEQ + l
    int l  = ml & (SEQ - 1);

    double inv = pow(10000.0, -(double)j / 32.0);
    double ang = (double)l * inv;
    float c = (float)cos(ang);
    float s = (float)sin(ang);

    size_t base = (size_t)ml * DIM + h * HD + j;
    float q1 = q[base], q2 = q[base + 32];
    q[base]      = q1 * c - q2 * s;
    q[base + 32] = q2 * c + q1 * s;
    float k1 = k[base], k2 = k[base + 32];
    k[base]      = k1 * c - k2 * s;
    k[base + 32] = k2 * c + k1 * s;
}

// ============================================================================
// S[bh,q,k] = (Q[b,q,h,:] . K[b,k,h,:]) * 0.125
// grid (SEQ/32, SEQ/32, B*NH), block (32,32)
// ============================================================================
__global__ void qk_kernel(const float* __restrict__ Q,
                          const float* __restrict__ K,
                          float* __restrict__ S)
{
    __shared__ float Qs[32][65];
    __shared__ float Ks[32][65];

    const int bh = blockIdx.z;
    const int b  = bh / NH;
    const int h  = bh - b * NH;
    const int tx = threadIdx.x;   // k within tile
    const int ty = threadIdx.y;   // q within tile
    const int q0 = blockIdx.y * 32;
    const int k0 = blockIdx.x * 32;

    // load 32x64 Q tile and 32x64 K tile (each thread 2 elems per tile)
    Qs[ty][tx]      = Q[(size_t)(b * SEQ + q0 + ty) * DIM + h * HD + tx];
    Qs[ty][tx + 32] = Q[(size_t)(b * SEQ + q0 + ty) * DIM + h * HD + tx + 32];
    Ks[ty][tx]      = K[(size_t)(b * SEQ + k0 + ty) * DIM + h * HD + tx];
    Ks[ty][tx + 32] = K[(size_t)(b * SEQ + k0 + ty) * DIM + h * HD + tx + 32];
    __syncthreads();

    float acc = 0.f;
    #pragma unroll 8
    for (int d = 0; d < HD; d++)
        acc = fmaf(Qs[ty][d], Ks[tx][d], acc);

    S[((size_t)bh * SEQ + q0 + ty) * SEQ + k0 + tx] = acc * 0.125f;
}

// ============================================================================
// Row softmax over SEQ=2048, one block (256 threads) per row. Two-pass.
// ============================================================================
__global__ void softmax_kernel(float* __restrict__ S)
{
    __shared__ float red[256];
    const size_t row = blockIdx.x;          // B*NH*SEQ rows
    float* p = S + row * SEQ;
    const int t = threadIdx.x;

    float mx = -1e30f;
    for (int i = t; i < SEQ; i += 256) mx = fmaxf(mx, p[i]);
    red[t] = mx; __syncthreads();
    for (int s = 128; s > 0; s >>= 1) {
        if (t < s) red[t] = fmaxf(red[t], red[t + s]);
        __syncthreads();
    }
    mx = red[0]; __syncthreads();

    float sum = 0.f;
    for (int i = t; i < SEQ; i += 256) {
        float e = __expf(p[i] - mx);
        p[i] = e;
        sum += e;
    }
    red[t] = sum; __syncthreads();
    for (int s = 128; s > 0; s >>= 1) {
        if (t < s) red[t] += red[t + s];
        __syncthreads();
    }
    float inv = 1.f / red[0];
    for (int i = t; i < SEQ; i += 256) p[i] *= inv;
}

// ============================================================================
// O[b,q,h,:] = sum_k P[bh,q,k] * V[b,k,h,:]
// grid (SEQ/8, B*NH), block (64, 8): thread -> output (q = bx*8+ty, d = tx)
// ============================================================================
__global__ void pv_kernel(const float* __restrict__ S,
                          const float* __restrict__ V,
                          float* __restrict__ O)
{
    __shared__ float Vt[64][65];
    __shared__ float Pt[8][65];

    const int bh = blockIdx.y;
    const int b  = bh / NH;
    const int h  = bh - b * NH;
    const int tx = threadIdx.x;   // d in [0,64)
    const int ty = threadIdx.y;   // q in tile [0,8)
    const int q  = blockIdx.x * 8 + ty;

    const float* srow = S + ((size_t)bh * SEQ + q) * SEQ;

    float acc = 0.f;
    for (int k0 = 0; k0 < SEQ; k0 += 64) {
        #pragma unroll
        for (int r = ty; r < 64; r += 8)
            Vt[r][tx] = V[(size_t)(b * SEQ + k0 + r) * DIM + h * HD + tx];
        Pt[ty][tx] = srow[k0 + tx];
        __syncthreads();
        #pragma unroll 8
        for (int kk = 0; kk < 64; kk++)
            acc = fmaf(Pt[ty][kk], Vt[kk][tx], acc);
        __syncthreads();
    }
    O[(size_t)(b * SEQ + q) * DIM + h * HD + tx] = acc;
}

// ============================================================================
extern "C" void kernel_launch(void* const* d_in, const int* in_sizes, int n_in,
                              void* d_out, int out_size)
{
    // Identify x by element count; weights are the remaining inputs in order.
    int xi = 0;
    for (int i = 0; i < n_in; i++)
        if (in_sizes[i] == M_TOTAL * DIM) { xi = i; break; }
    const float* x = (const float*)d_in[xi];
    const float* Wm[4];
    int wn = 0;
    for (int i = 0; i < n_in && wn < 4; i++)
        if (i != xi) Wm[wn++] = (const float*)d_in[i];
    const float* Wq = Wm[0];
    const float* Wk = Wm[1];
    const float* Wv = Wm[2];
    const float* Wo = Wm[3];
    float* out = (float*)d_out;

    float *q, *k, *v, *attn, *s;
    cudaGetSymbolAddress((void**)&q,    g_q);
    cudaGetSymbolAddress((void**)&k,    g_k);
    cudaGetSymbolAddress((void**)&v,    g_v);
    cudaGetSymbolAddress((void**)&attn, g_attn);
    cudaGetSymbolAddress((void**)&s,    g_s);

    dim3 gblk(32, 32);
    dim3 ggrid(DIM / 32, M_TOTAL / 32);          // (32, 256)
    gemm32_kernel<<<ggrid, gblk>>>(x, Wq, q);
    gemm32_kernel<<<ggrid, gblk>>>(x, Wk, k);
    gemm32_kernel<<<ggrid, gblk>>>(x, Wv, v);

    rope_kernel<<<(M_TOTAL * NH * 32) / 256, 256>>>(q, k);

    qk_kernel<<<dim3(SEQ / 32, SEQ / 32, BATCH * NH), dim3(32, 32)>>>(q, k, s);
    softmax_kernel<<<BATCH * NH * SEQ, 256>>>(s);
    pv_kernel<<<dim3(SEQ / 8, BATCH * NH), dim3(64, 8)>>>(s, v, attn);

    gemm32_kernel<<<ggrid, gblk>>>(attn, Wo, out);
}

// round 8
// speedup vs baseline: 5.6079x; 5.6079x over previous
#include <cuda_runtime.h>
#include <cuda_bf16.h>
#include <math.h>

#define BATCH 4
#define SEQ   2048
#define DIM   1024
#define NH    16
#define HD    64
#define M_TOTAL (BATCH*SEQ)

typedef unsigned long long u64;

// Scratch (device globals; no runtime allocation allowed)
__device__ float g_q[M_TOTAL*DIM];
__device__ float g_k[M_TOTAL*DIM];
__device__ float g_v[M_TOTAL*DIM];
__device__ float g_attn[M_TOTAL*DIM];
__device__ float g_s[(size_t)BATCH*NH*SEQ*SEQ];     // 1 GiB scores
__device__ float g_cos[SEQ*32];
__device__ float g_sin[SEQ*32];

// ---------- packed f32x2 helpers ----------
__device__ __forceinline__ u64 ffma2(u64 a, u64 b, u64 c) {
    u64 d; asm("fma.rn.f32x2 %0, %1, %2, %3;" : "=l"(d) : "l"(a), "l"(b), "l"(c)); return d;
}
__device__ __forceinline__ u64 fmul2(u64 a, u64 b) {
    u64 d; asm("mul.rn.f32x2 %0, %1, %2;" : "=l"(d) : "l"(a), "l"(b)); return d;
}
__device__ __forceinline__ u64 pack2(float x, float y) {
    u64 d; asm("mov.b64 %0, {%1, %2};" : "=l"(d) : "f"(x), "f"(y)); return d;
}

// ============================================================================
// Fast SGEMM: C[M,1024] = A[M,1024] @ W[1024,1024]^T (both K-major)
// 128x128x16 tile, 256 threads, 8x8 outputs/thread, f32x2 along N.
// ============================================================================
#define GBK 16
#define GP  132

__global__ __launch_bounds__(256, 2)
void gemm_nt_kernel(const float* __restrict__ A, const float* __restrict__ W,
                    float* __restrict__ C)
{
    __shared__ float Ast[GBK][GP];
    __shared__ float Ws [GBK][GP];

    const int tid = threadIdx.x;
    const int tx  = tid & 15;
    const int ty  = tid >> 4;
    const int m0  = blockIdx.y * 128;
    const int n0  = blockIdx.x * 128;

    u64 acc[8][4];
    #pragma unroll
    for (int i = 0; i < 8; i++)
        #pragma unroll
        for (int j = 0; j < 4; j++) acc[i][j] = 0ull;

    for (int kb = 0; kb < DIM; kb += GBK) {
        #pragma unroll
        for (int p = 0; p < 2; p++) {
            int q  = p * 256 + tid;
            int m  = q >> 2;
            int k4 = (q & 3) << 2;
            float4 v = *reinterpret_cast<const float4*>(&A[(size_t)(m0 + m) * DIM + kb + k4]);
            Ast[k4+0][m] = v.x; Ast[k4+1][m] = v.y; Ast[k4+2][m] = v.z; Ast[k4+3][m] = v.w;
        }
        #pragma unroll
        for (int p = 0; p < 2; p++) {
            int q  = p * 256 + tid;
            int n  = q >> 2;
            int k4 = (q & 3) << 2;
            float4 v = *reinterpret_cast<const float4*>(&W[(size_t)(n0 + n) * DIM + kb + k4]);
            Ws[k4+0][n] = v.x; Ws[k4+1][n] = v.y; Ws[k4+2][n] = v.z; Ws[k4+3][n] = v.w;
        }
        __syncthreads();

        #pragma unroll
        for (int k = 0; k < GBK; k++) {
            float4 a0 = *reinterpret_cast<const float4*>(&Ast[k][ty * 4]);
            float4 a1 = *reinterpret_cast<const float4*>(&Ast[k][64 + ty * 4]);
            u64 b0 = *reinterpret_cast<const u64*>(&Ws[k][tx * 4]);
            u64 b1 = *reinterpret_cast<const u64*>(&Ws[k][tx * 4 + 2]);
            u64 b2 = *reinterpret_cast<const u64*>(&Ws[k][64 + tx * 4]);
            u64 b3 = *reinterpret_cast<const u64*>(&Ws[k][64 + tx * 4 + 2]);
            float af[8] = {a0.x, a0.y, a0.z, a0.w, a1.x, a1.y, a1.z, a1.w};
            #pragma unroll
            for (int i = 0; i < 8; i++) {
                u64 aa = pack2(af[i], af[i]);
                acc[i][0] = ffma2(aa, b0, acc[i][0]);
                acc[i][1] = ffma2(aa, b1, acc[i][1]);
                acc[i][2] = ffma2(aa, b2, acc[i][2]);
                acc[i][3] = ffma2(aa, b3, acc[i][3]);
            }
        }
        __syncthreads();
    }

    #pragma unroll
    for (int i = 0; i < 8; i++) {
        int m = m0 + ((i < 4) ? (ty * 4 + i) : (64 + ty * 4 + (i - 4)));
        u64* crow = reinterpret_cast<u64*>(&C[(size_t)m * DIM + n0]);
        crow[tx * 2]          = acc[i][0];
        crow[tx * 2 + 1]      = acc[i][1];
        crow[32 + tx * 2]     = acc[i][2];
        crow[32 + tx * 2 + 1] = acc[i][3];
    }
}

// ============================================================================
// RoPE tables (double trig done once per (l,j), not per (b,h,l,j))
// ============================================================================
__global__ void rope_table_kernel(float* __restrict__ gc, float* __restrict__ gs)
{
    int idx = blockIdx.x * blockDim.x + threadIdx.x;   // 65536
    int j = idx & 31;
    int l = idx >> 5;
    double inv = pow(10000.0, -(double)j / 32.0);
    double ang = (double)l * inv;
    gc[idx] = (float)cos(ang);
    gs[idx] = (float)sin(ang);
}

__global__ void rope_kernel(float* __restrict__ q, float* __restrict__ k,
                            const float* __restrict__ gc, const float* __restrict__ gs)
{
    int idx = blockIdx.x * blockDim.x + threadIdx.x;   // M_TOTAL*NH*32
    int j  = idx & 31;
    int h  = (idx >> 5) & (NH - 1);
    int ml = idx >> 9;
    int l  = ml & (SEQ - 1);

    float c = gc[l * 32 + j];
    float s = gs[l * 32 + j];

    size_t base = (size_t)ml * DIM + h * HD + j;
    float q1 = q[base], q2 = q[base + 32];
    q[base]      = q1 * c - q2 * s;
    q[base + 32] = q2 * c + q1 * s;
    float k1 = k[base], k2 = k[base + 32];
    k[base]      = k1 * c - k2 * s;
    k[base + 32] = k2 * c + k1 * s;
}

// ============================================================================
// QK: S[bh, q, k] = 0.125 * dot(Q[b,q,h,:], K[b,k,h,:])
// 128x128 tile per block over (q,k), K-dim = 64 in two 32-chunks, f32x2.
// ============================================================================
__global__ __launch_bounds__(256, 2)
void qk_kernel(const float* __restrict__ Q, const float* __restrict__ K,
               float* __restrict__ S)
{
    __shared__ float Qs[32][GP];
    __shared__ float Ks[32][GP];

    const int tid = threadIdx.x;
    const int tx  = tid & 15;
    const int ty  = tid >> 4;
    const int bh  = blockIdx.z;
    const int b   = bh >> 4;
    const int h   = bh & 15;
    const int m0  = blockIdx.y * 128;   // q base
    const int n0  = blockIdx.x * 128;   // k base

    const float* qb = Q + (size_t)(b * SEQ + m0) * DIM + h * HD;
    const float* kb = K + (size_t)(b * SEQ + n0) * DIM + h * HD;

    u64 acc[8][4];
    #pragma unroll
    for (int i = 0; i < 8; i++)
        #pragma unroll
        for (int j = 0; j < 4; j++) acc[i][j] = 0ull;

    #pragma unroll
    for (int d0 = 0; d0 < HD; d0 += 32) {
        #pragma unroll
        for (int p = 0; p < 4; p++) {
            int idx = p * 256 + tid;          // 1024 float4 slots
            int m   = idx >> 3;
            int d4  = (idx & 7) << 2;
            float4 v = *reinterpret_cast<const float4*>(&qb[(size_t)m * DIM + d0 + d4]);
            Qs[d4+0][m] = v.x; Qs[d4+1][m] = v.y; Qs[d4+2][m] = v.z; Qs[d4+3][m] = v.w;
            float4 w = *reinterpret_cast<const float4*>(&kb[(size_t)m * DIM + d0 + d4]);
            Ks[d4+0][m] = w.x; Ks[d4+1][m] = w.y; Ks[d4+2][m] = w.z; Ks[d4+3][m] = w.w;
        }
        __syncthreads();

        #pragma unroll
        for (int k = 0; k < 32; k++) {
            float4 a0 = *reinterpret_cast<const float4*>(&Qs[k][ty * 4]);
            float4 a1 = *reinterpret_cast<const float4*>(&Qs[k][64 + ty * 4]);
            u64 b0 = *reinterpret_cast<const u64*>(&Ks[k][tx * 4]);
            u64 b1 = *reinterpret_cast<const u64*>(&Ks[k][tx * 4 + 2]);
            u64 b2 = *reinterpret_cast<const u64*>(&Ks[k][64 + tx * 4]);
            u64 b3 = *reinterpret_cast<const u64*>(&Ks[k][64 + tx * 4 + 2]);
            float af[8] = {a0.x, a0.y, a0.z, a0.w, a1.x, a1.y, a1.z, a1.w};
            #pragma unroll
            for (int i = 0; i < 8; i++) {
                u64 aa = pack2(af[i], af[i]);
                acc[i][0] = ffma2(aa, b0, acc[i][0]);
                acc[i][1] = ffma2(aa, b1, acc[i][1]);
                acc[i][2] = ffma2(aa, b2, acc[i][2]);
                acc[i][3] = ffma2(aa, b3, acc[i][3]);
            }
        }
        __syncthreads();
    }

    const u64 sc2 = pack2(0.125f, 0.125f);
    #pragma unroll
    for (int i = 0; i < 8; i++) {
        int m = m0 + ((i < 4) ? (ty * 4 + i) : (64 + ty * 4 + (i - 4)));
        u64* srow = reinterpret_cast<u64*>(&S[((size_t)bh * SEQ + m) * SEQ + n0]);
        srow[tx * 2]          = fmul2(acc[i][0], sc2);
        srow[tx * 2 + 1]      = fmul2(acc[i][1], sc2);
        srow[32 + tx * 2]     = fmul2(acc[i][2], sc2);
        srow[32 + tx * 2 + 1] = fmul2(acc[i][3], sc2);
    }
}

// ============================================================================
// Row softmax over SEQ=2048; 256 threads/row, register-resident (8/thread).
// ============================================================================
__global__ __launch_bounds__(256)
void softmax_kernel(float* __restrict__ S)
{
    __shared__ float red[8];
    float* p = S + (size_t)blockIdx.x * SEQ;
    const int t    = threadIdx.x;
    const int lane = t & 31;
    const int warp = t >> 5;

    float x[8];
    #pragma unroll
    for (int j = 0; j < 8; j++) x[j] = p[t + 256 * j];

    float mx = x[0];
    #pragma unroll
    for (int j = 1; j < 8; j++) mx = fmaxf(mx, x[j]);
    #pragma unroll
    for (int o = 16; o > 0; o >>= 1) mx = fmaxf(mx, __shfl_xor_sync(0xffffffffu, mx, o));
    if (lane == 0) red[warp] = mx;
    __syncthreads();
    mx = red[0];
    #pragma unroll
    for (int w = 1; w < 8; w++) mx = fmaxf(mx, red[w]);
    __syncthreads();

    float sum = 0.f;
    #pragma unroll
    for (int j = 0; j < 8; j++) { x[j] = __expf(x[j] - mx); sum += x[j]; }
    #pragma unroll
    for (int o = 16; o > 0; o >>= 1) sum += __shfl_xor_sync(0xffffffffu, sum, o);
    if (lane == 0) red[warp] = sum;
    __syncthreads();
    sum = red[0];
    #pragma unroll
    for (int w = 1; w < 8; w++) sum += red[w];

    float inv = 1.f / sum;
    #pragma unroll
    for (int j = 0; j < 8; j++) p[t + 256 * j] = x[j] * inv;
}

// ============================================================================
// PV: O[b,q,h,:] = sum_k P[bh,q,k] V[b,k,h,:]
// Block = 128 q x 64 d per bh; K=2048 in 32-chunks; 8x4 outputs/thread, f32x2.
// ============================================================================
__global__ __launch_bounds__(256, 2)
void pv_kernel(const float* __restrict__ P, const float* __restrict__ V,
               float* __restrict__ O)
{
    __shared__ float Pt[32][GP];    // [k][q]
    __shared__ float Vs[32][68];    // [k][d]

    const int tid = threadIdx.x;
    const int tx  = tid & 15;       // d group: d0 = tx*4
    const int ty  = tid >> 4;       // q group: q = ty*8 + i
    const int bh  = blockIdx.y;
    const int b   = bh >> 4;
    const int h   = bh & 15;
    const int q0  = blockIdx.x * 128;

    const float* pb = P + ((size_t)bh * SEQ + q0) * SEQ;
    const float* vb = V + (size_t)(b * SEQ) * DIM + h * HD;

    u64 acc[8][2];
    #pragma unroll
    for (int i = 0; i < 8; i++) { acc[i][0] = 0ull; acc[i][1] = 0ull; }

    for (int k0 = 0; k0 < SEQ; k0 += 32) {
        #pragma unroll
        for (int p = 0; p < 4; p++) {
            int idx = p * 256 + tid;          // 1024 float4 slots (128q x 8)
            int qr  = idx >> 3;
            int k4  = (idx & 7) << 2;
            float4 v = *reinterpret_cast<const float4*>(&pb[(size_t)qr * SEQ + k0 + k4]);
            Pt[k4+0][qr] = v.x; Pt[k4+1][qr] = v.y; Pt[k4+2][qr] = v.z; Pt[k4+3][qr] = v.w;
        }
        #pragma unroll
        for (int p = 0; p < 2; p++) {
            int idx = p * 256 + tid;          // 512 float4 slots (32k x 16)
            int kr  = idx >> 4;
            int d4  = (idx & 15) << 2;
            *reinterpret_cast<float4*>(&Vs[kr][d4]) =
                *reinterpret_cast<const float4*>(&vb[(size_t)(k0 + kr) * DIM + d4]);
        }
        __syncthreads();

        #pragma unroll
        for (int kk = 0; kk < 32; kk++) {
            u64 v0 = *reinterpret_cast<const u64*>(&Vs[kk][tx * 4]);
            u64 v1 = *reinterpret_cast<const u64*>(&Vs[kk][tx * 4 + 2]);
            #pragma unroll
            for (int i = 0; i < 8; i++) {
                float pr = Pt[kk][ty * 8 + i];
                u64 pp = pack2(pr, pr);
                acc[i][0] = ffma2(pp, v0, acc[i][0]);
                acc[i][1] = ffma2(pp, v1, acc[i][1]);
            }
        }
        __syncthreads();
    }

    #pragma unroll
    for (int i = 0; i < 8; i++) {
        int q = q0 + ty * 8 + i;
        u64* orow = reinterpret_cast<u64*>(&O[(size_t)(b * SEQ + q) * DIM + h * HD]);
        orow[tx * 2]     = acc[i][0];
        orow[tx * 2 + 1] = acc[i][1];
    }
}

// ============================================================================
extern "C" void kernel_launch(void* const* d_in, const int* in_sizes, int n_in,
                              void* d_out, int out_size)
{
    // Identify x by element count; weights are the remaining inputs in order.
    int xi = 0;
    for (int i = 0; i < n_in; i++)
        if (in_sizes[i] == M_TOTAL * DIM) { xi = i; break; }
    const float* x = (const float*)d_in[xi];
    const float* Wm[4];
    int wn = 0;
    for (int i = 0; i < n_in && wn < 4; i++)
        if (i != xi) Wm[wn++] = (const float*)d_in[i];
    const float* Wq = Wm[0];
    const float* Wk = Wm[1];
    const float* Wv = Wm[2];
    const float* Wo = Wm[3];
    float* out = (float*)d_out;

    float *q, *k, *v, *attn, *s, *gc, *gs;
    cudaGetSymbolAddress((void**)&q,    g_q);
    cudaGetSymbolAddress((void**)&k,    g_k);
    cudaGetSymbolAddress((void**)&v,    g_v);
    cudaGetSymbolAddress((void**)&attn, g_attn);
    cudaGetSymbolAddress((void**)&s,    g_s);
    cudaGetSymbolAddress((void**)&gc,   g_cos);
    cudaGetSymbolAddress((void**)&gs,   g_sin);

    dim3 ggrid(DIM / 128, M_TOTAL / 128);        // (8, 64)
    gemm_nt_kernel<<<ggrid, 256>>>(x, Wq, q);
    gemm_nt_kernel<<<ggrid, 256>>>(x, Wk, k);
    gemm_nt_kernel<<<ggrid, 256>>>(x, Wv, v);

    rope_table_kernel<<<SEQ * 32 / 256, 256>>>(gc, gs);
    rope_kernel<<<(M_TOTAL * NH * 32) / 256, 256>>>(q, k, gc, gs);

    qk_kernel<<<dim3(SEQ / 128, SEQ / 128, BATCH * NH), 256>>>(q, k, s);
    softmax_kernel<<<BATCH * NH * SEQ, 256>>>(s);
    pv_kernel<<<dim3(SEQ / 128, BATCH * NH), 256>>>(s, v, attn);

    gemm_nt_kernel<<<ggrid, 256>>>(attn, Wo, out);
}

// round 11
// speedup vs baseline: 6.8984x; 1.2301x over previous
#include <cuda_runtime.h>
#include <cuda_bf16.h>
#include <math.h>

#define BATCH 4
#define SEQ   2048
#define DIM   1024
#define NH    16
#define HD    64
#define M_TOTAL (BATCH*SEQ)
#define K3    (3*DIM)          // [Ah | Al | Ah] x [Bh | Bh | Bl]

typedef unsigned long long u64;
typedef unsigned int u32;

// ---------------- device scratch ----------------
__device__ float g_q[M_TOTAL*DIM];
__device__ float g_k[M_TOTAL*DIM];
__device__ float g_v[M_TOTAL*DIM];
__device__ float g_attn[M_TOTAL*DIM];
__device__ float g_s[(size_t)BATCH*NH*SEQ*SEQ];     // 1 GiB scores
__device__ float g_cos[SEQ*32];
__device__ float g_sin[SEQ*32];
__device__ __nv_bfloat16 g_x3[(size_t)M_TOTAL*K3];  // [M][3072] = [hi | lo | hi]
__device__ __nv_bfloat16 g_w3[(size_t)4*DIM*K3];    // 4 x [1024][3072] = [hi | hi | lo]

// ---------------- packed f32x2 helpers ----------------
__device__ __forceinline__ u64 ffma2(u64 a, u64 b, u64 c) {
    u64 d; asm("fma.rn.f32x2 %0, %1, %2, %3;" : "=l"(d) : "l"(a), "l"(b), "l"(c)); return d;
}
__device__ __forceinline__ u64 fmul2(u64 a, u64 b) {
    u64 d; asm("mul.rn.f32x2 %0, %1, %2;" : "=l"(d) : "l"(a), "l"(b)); return d;
}
__device__ __forceinline__ u64 pack2(float x, float y) {
    u64 d; asm("mov.b64 %0, {%1, %2};" : "=l"(d) : "f"(x), "f"(y)); return d;
}

// ---------------- mma.sync helpers ----------------
__device__ __forceinline__ u32 smem_u32(const void* p) {
    u32 a;
    asm("{ .reg .u64 t; cvta.to.shared.u64 t, %1; cvt.u32.u64 %0, t; }" : "=r"(a) : "l"(p));
    return a;
}
__device__ __forceinline__ void ldsm_x4(u32& r0, u32& r1, u32& r2, u32& r3, u32 addr) {
    asm volatile("ldmatrix.sync.aligned.m8n8.x4.shared.b16 {%0,%1,%2,%3}, [%4];"
                 : "=r"(r0), "=r"(r1), "=r"(r2), "=r"(r3) : "r"(addr));
}
__device__ __forceinline__ void mma16816(float* c, const u32* a, u32 b0, u32 b1) {
    asm volatile(
        "mma.sync.aligned.m16n8k16.row.col.f32.bf16.bf16.f32 "
        "{%0,%1,%2,%3}, {%4,%5,%6,%7}, {%8,%9}, {%0,%1,%2,%3};"
        : "+f"(c[0]), "+f"(c[1]), "+f"(c[2]), "+f"(c[3])
        : "r"(a[0]), "r"(a[1]), "r"(a[2]), "r"(a[3]), "r"(b0), "r"(b1));
}
__device__ __forceinline__ void cpasync16(u32 dst, const void* src) {
    asm volatile("cp.async.cg.shared.global [%0], [%1], 16;" :: "r"(dst), "l"(src));
}

// ============================================================================
// Split fp32 -> bf16 three-segment row (pitch 3072).
// hi written at +0 and +hi2_off, lo at +lo_off.
//   activations: hi2_off = 2*DIM, lo_off = DIM   -> [hi | lo | hi]
//   weights:     hi2_off = DIM,   lo_off = 2*DIM -> [hi | hi | lo]
// ============================================================================
__global__ void split_kernel(const float* __restrict__ src,
                             __nv_bfloat16* __restrict__ dst, int n4,
                             int hi2_off, int lo_off)
{
    int i = blockIdx.x * blockDim.x + threadIdx.x;
    if (i >= n4) return;
    const int cols4 = DIM / 4;
    int r = i / cols4;
    int c = (i - r * cols4) * 4;
    float4 v = reinterpret_cast<const float4*>(src)[i];
    __nv_bfloat16 h0 = __float2bfloat16(v.x);
    __nv_bfloat16 h1 = __float2bfloat16(v.y);
    __nv_bfloat16 h2 = __float2bfloat16(v.z);
    __nv_bfloat16 h3 = __float2bfloat16(v.w);
    __nv_bfloat16 l0 = __float2bfloat16(v.x - __bfloat162float(h0));
    __nv_bfloat16 l1 = __float2bfloat16(v.y - __bfloat162float(h1));
    __nv_bfloat16 l2 = __float2bfloat16(v.z - __bfloat162float(h2));
    __nv_bfloat16 l3 = __float2bfloat16(v.w - __bfloat162float(h3));
    __nv_bfloat162 hp[2] = {__nv_bfloat162(h0, h1), __nv_bfloat162(h2, h3)};
    __nv_bfloat162 lp[2] = {__nv_bfloat162(l0, l1), __nv_bfloat162(l2, l3)};
    uint2 hv = *reinterpret_cast<uint2*>(hp);
    uint2 lv = *reinterpret_cast<uint2*>(lp);
    size_t base = (size_t)r * K3 + c;
    *reinterpret_cast<uint2*>(&dst[base])           = hv;
    *reinterpret_cast<uint2*>(&dst[base + hi2_off]) = hv;
    *reinterpret_cast<uint2*>(&dst[base + lo_off])  = lv;
}

// ============================================================================
// HMMA bf16 GEMM: C[M,1024] = A3[M,3072] @ B3[1024,3072]^T  (NT, K-major)
// 128x128 tile, 256 thr, 8 warps (2M x 4N), 64x32/warp via m16n8k16.
// cp.async double-buffered smem, pitch 40 bf16 (conflict-free ldmatrix).
// ============================================================================
#define PITCH 40
#define KB    32
#define STG_ELE (128*PITCH)

__global__ __launch_bounds__(256)
void hmma_gemm_kernel(const __nv_bfloat16* __restrict__ A3,
                      const __nv_bfloat16* __restrict__ B3,
                      float* __restrict__ C)
{
    __shared__ __nv_bfloat16 smA[2][STG_ELE];
    __shared__ __nv_bfloat16 smB[2][STG_ELE];

    const int tid  = threadIdx.x;
    const int wid  = tid >> 5;
    const int lane = tid & 31;
    const int wm   = wid & 1;          // 0..1  (64 rows each)
    const int wn   = wid >> 1;         // 0..3  (32 cols each)
    const int m0   = blockIdx.y * 128;
    const int n0   = blockIdx.x * 128;

    const u32 baseA = smem_u32(smA);
    const u32 baseB = smem_u32(smB);

    const __nv_bfloat16* Ag = A3 + (size_t)m0 * K3;
    const __nv_bfloat16* Bg = B3 + (size_t)n0 * K3;

    const int crow0 = (tid)       >> 2, cseg0 = (tid)       & 3;
    const int crow1 = (tid + 256) >> 2, cseg1 = (tid + 256) & 3;

    auto load_stage = [&](int st, int k0) {
        u32 dA = baseA + st * (STG_ELE * 2);
        u32 dB = baseB + st * (STG_ELE * 2);
        cpasync16(dA + (crow0 * PITCH + cseg0 * 8) * 2, &Ag[(size_t)crow0 * K3 + k0 + cseg0 * 8]);
        cpasync16(dA + (crow1 * PITCH + cseg1 * 8) * 2, &Ag[(size_t)crow1 * K3 + k0 + cseg1 * 8]);
        cpasync16(dB + (crow0 * PITCH + cseg0 * 8) * 2, &Bg[(size_t)crow0 * K3 + k0 + cseg0 * 8]);
        cpasync16(dB + (crow1 * PITCH + cseg1 * 8) * 2, &Bg[(size_t)crow1 * K3 + k0 + cseg1 * 8]);
    };

    float acc[4][4][4];
    #pragma unroll
    for (int i = 0; i < 4; i++)
        #pragma unroll
        for (int j = 0; j < 4; j++)
            #pragma unroll
            for (int e = 0; e < 4; e++) acc[i][j][e] = 0.f;

    const int mi = lane >> 3, mr = lane & 7;
    const int arow_off = (mi & 1) * 8 + mr;
    const int acol_off = (mi >> 1) * 8;
    const int brow_off = (mi >> 1) * 8 + mr;
    const int bcol_off = (mi & 1) * 8;

    load_stage(0, 0);
    asm volatile("cp.async.commit_group;");

    const int NIT = K3 / KB;   // 96
    for (int it = 0; it < NIT; it++) {
        if (it + 1 < NIT) load_stage((it + 1) & 1, (it + 1) * KB);
        asm volatile("cp.async.commit_group;");
        asm volatile("cp.async.wait_group 1;");
        __syncthreads();

        const int st = it & 1;
        const u32 sA = baseA + st * (STG_ELE * 2);
        const u32 sB = baseB + st * (STG_ELE * 2);

        #pragma unroll
        for (int ks = 0; ks < 2; ks++) {
            u32 a[4][4], b[2][4];
            #pragma unroll
            for (int tm = 0; tm < 4; tm++) {
                int row = wm * 64 + tm * 16 + arow_off;
                ldsm_x4(a[tm][0], a[tm][1], a[tm][2], a[tm][3],
                        sA + (row * PITCH + ks * 16 + acol_off) * 2);
            }
            #pragma unroll
            for (int tp = 0; tp < 2; tp++) {
                int row = wn * 32 + tp * 16 + brow_off;
                ldsm_x4(b[tp][0], b[tp][1], b[tp][2], b[tp][3],
                        sB + (row * PITCH + ks * 16 + bcol_off) * 2);
            }
            #pragma unroll
            for (int tm = 0; tm < 4; tm++)
                #pragma unroll
                for (int tn = 0; tn < 4; tn++)
                    mma16816(acc[tm][tn], a[tm], b[tn >> 1][(tn & 1) * 2], b[tn >> 1][(tn & 1) * 2 + 1]);
        }
        __syncthreads();
    }

    const int gid = lane >> 2, tig = lane & 3;
    #pragma unroll
    for (int tm = 0; tm < 4; tm++) {
        #pragma unroll
        for (int tn = 0; tn < 4; tn++) {
            int row = m0 + wm * 64 + tm * 16 + gid;
            int col = n0 + wn * 32 + tn * 8 + tig * 2;
            *reinterpret_cast<float2*>(&C[(size_t)row * DIM + col]) =
                make_float2(acc[tm][tn][0], acc[tm][tn][1]);
            *reinterpret_cast<float2*>(&C[(size_t)(row + 8) * DIM + col]) =
                make_float2(acc[tm][tn][2], acc[tm][tn][3]);
        }
    }
}

// ============================================================================
// RoPE tables + RoPE (unchanged)
// ============================================================================
__global__ void rope_table_kernel(float* __restrict__ gc, float* __restrict__ gs)
{
    int idx = blockIdx.x * blockDim.x + threadIdx.x;
    int j = idx & 31;
    int l = idx >> 5;
    double inv = pow(10000.0, -(double)j / 32.0);
    double ang = (double)l * inv;
    gc[idx] = (float)cos(ang);
    gs[idx] = (float)sin(ang);
}

__global__ void rope_kernel(float* __restrict__ q, float* __restrict__ k,
                            const float* __restrict__ gc, const float* __restrict__ gs)
{
    int idx = blockIdx.x * blockDim.x + threadIdx.x;
    int j  = idx & 31;
    int h  = (idx >> 5) & (NH - 1);
    int ml = idx >> 9;
    int l  = ml & (SEQ - 1);

    float c = gc[l * 32 + j];
    float s = gs[l * 32 + j];

    size_t base = (size_t)ml * DIM + h * HD + j;
    float q1 = q[base], q2 = q[base + 32];
    q[base]      = q1 * c - q2 * s;
    q[base + 32] = q2 * c + q1 * s;
    float k1 = k[base], k2 = k[base + 32];
    k[base]      = k1 * c - k2 * s;
    k[base + 32] = k2 * c + k1 * s;
}

// ============================================================================
// QK (unchanged from R8)
// ============================================================================
#define GP 132

__global__ __launch_bounds__(256, 2)
void qk_kernel(const float* __restrict__ Q, const float* __restrict__ K,
               float* __restrict__ S)
{
    __shared__ float Qs[32][GP];
    __shared__ float Ks[32][GP];

    const int tid = threadIdx.x;
    const int tx  = tid & 15;
    const int ty  = tid >> 4;
    const int bh  = blockIdx.z;
    const int b   = bh >> 4;
    const int h   = bh & 15;
    const int m0  = blockIdx.y * 128;
    const int n0  = blockIdx.x * 128;

    const float* qb = Q + (size_t)(b * SEQ + m0) * DIM + h * HD;
    const float* kb = K + (size_t)(b * SEQ + n0) * DIM + h * HD;

    u64 acc[8][4];
    #pragma unroll
    for (int i = 0; i < 8; i++)
        #pragma unroll
        for (int j = 0; j < 4; j++) acc[i][j] = 0ull;

    #pragma unroll
    for (int d0 = 0; d0 < HD; d0 += 32) {
        #pragma unroll
        for (int p = 0; p < 4; p++) {
            int idx = p * 256 + tid;
            int m   = idx >> 3;
            int d4  = (idx & 7) << 2;
            float4 v = *reinterpret_cast<const float4*>(&qb[(size_t)m * DIM + d0 + d4]);
            Qs[d4+0][m] = v.x; Qs[d4+1][m] = v.y; Qs[d4+2][m] = v.z; Qs[d4+3][m] = v.w;
            float4 w = *reinterpret_cast<const float4*>(&kb[(size_t)m * DIM + d0 + d4]);
            Ks[d4+0][m] = w.x; Ks[d4+1][m] = w.y; Ks[d4+2][m] = w.z; Ks[d4+3][m] = w.w;
        }
        __syncthreads();

        #pragma unroll
        for (int k = 0; k < 32; k++) {
            float4 a0 = *reinterpret_cast<const float4*>(&Qs[k][ty * 4]);
            float4 a1 = *reinterpret_cast<const float4*>(&Qs[k][64 + ty * 4]);
            u64 b0 = *reinterpret_cast<const u64*>(&Ks[k][tx * 4]);
            u64 b1 = *reinterpret_cast<const u64*>(&Ks[k][tx * 4 + 2]);
            u64 b2 = *reinterpret_cast<const u64*>(&Ks[k][64 + tx * 4]);
            u64 b3 = *reinterpret_cast<const u64*>(&Ks[k][64 + tx * 4 + 2]);
            float af[8] = {a0.x, a0.y, a0.z, a0.w, a1.x, a1.y, a1.z, a1.w};
            #pragma unroll
            for (int i = 0; i < 8; i++) {
                u64 aa = pack2(af[i], af[i]);
                acc[i][0] = ffma2(aa, b0, acc[i][0]);
                acc[i][1] = ffma2(aa, b1, acc[i][1]);
                acc[i][2] = ffma2(aa, b2, acc[i][2]);
                acc[i][3] = ffma2(aa, b3, acc[i][3]);
            }
        }
        __syncthreads();
    }

    const u64 sc2 = pack2(0.125f, 0.125f);
    #pragma unroll
    for (int i = 0; i < 8; i++) {
        int m = m0 + ((i < 4) ? (ty * 4 + i) : (64 + ty * 4 + (i - 4)));
        u64* srow = reinterpret_cast<u64*>(&S[((size_t)bh * SEQ + m) * SEQ + n0]);
        srow[tx * 2]          = fmul2(acc[i][0], sc2);
        srow[tx * 2 + 1]      = fmul2(acc[i][1], sc2);
        srow[32 + tx * 2]     = fmul2(acc[i][2], sc2);
        srow[32 + tx * 2 + 1] = fmul2(acc[i][3], sc2);
    }
}

// ============================================================================
// Softmax (unchanged from R8)
// ============================================================================
__global__ __launch_bounds__(256)
void softmax_kernel(float* __restrict__ S)
{
    __shared__ float red[8];
    float* p = S + (size_t)blockIdx.x * SEQ;
    const int t    = threadIdx.x;
    const int lane = t & 31;
    const int warp = t >> 5;

    float x[8];
    #pragma unroll
    for (int j = 0; j < 8; j++) x[j] = p[t + 256 * j];

    float mx = x[0];
    #pragma unroll
    for (int j = 1; j < 8; j++) mx = fmaxf(mx, x[j]);
    #pragma unroll
    for (int o = 16; o > 0; o >>= 1) mx = fmaxf(mx, __shfl_xor_sync(0xffffffffu, mx, o));
    if (lane == 0) red[warp] = mx;
    __syncthreads();
    mx = red[0];
    #pragma unroll
    for (int w = 1; w < 8; w++) mx = fmaxf(mx, red[w]);
    __syncthreads();

    float sum = 0.f;
    #pragma unroll
    for (int j = 0; j < 8; j++) { x[j] = __expf(x[j] - mx); sum += x[j]; }
    #pragma unroll
    for (int o = 16; o > 0; o >>= 1) sum += __shfl_xor_sync(0xffffffffu, sum, o);
    if (lane == 0) red[warp] = sum;
    __syncthreads();
    sum = red[0];
    #pragma unroll
    for (int w = 1; w < 8; w++) sum += red[w];

    float inv = 1.f / sum;
    #pragma unroll
    for (int j = 0; j < 8; j++) p[t + 256 * j] = x[j] * inv;
}

// ============================================================================
// PV (unchanged from R8)
// ============================================================================
__global__ __launch_bounds__(256, 2)
void pv_kernel(const float* __restrict__ P, const float* __restrict__ V,
               float* __restrict__ O)
{
    __shared__ float Pt[32][GP];
    __shared__ float Vs[32][68];

    const int tid = threadIdx.x;
    const int tx  = tid & 15;
    const int ty  = tid >> 4;
    const int bh  = blockIdx.y;
    const int b   = bh >> 4;
    const int h   = bh & 15;
    const int q0  = blockIdx.x * 128;

    const float* pb = P + ((size_t)bh * SEQ + q0) * SEQ;
    const float* vb = V + (size_t)(b * SEQ) * DIM + h * HD;

    u64 acc[8][2];
    #pragma unroll
    for (int i = 0; i < 8; i++) { acc[i][0] = 0ull; acc[i][1] = 0ull; }

    for (int k0 = 0; k0 < SEQ; k0 += 32) {
        #pragma unroll
        for (int p = 0; p < 4; p++) {
            int idx = p * 256 + tid;
            int qr  = idx >> 3;
            int k4  = (idx & 7) << 2;
            float4 v = *reinterpret_cast<const float4*>(&pb[(size_t)qr * SEQ + k0 + k4]);
            Pt[k4+0][qr] = v.x; Pt[k4+1][qr] = v.y; Pt[k4+2][qr] = v.z; Pt[k4+3][qr] = v.w;
        }
        #pragma unroll
        for (int p = 0; p < 2; p++) {
            int idx = p * 256 + tid;
            int kr  = idx >> 4;
            int d4  = (idx & 15) << 2;
            *reinterpret_cast<float4*>(&Vs[kr][d4]) =
                *reinterpret_cast<const float4*>(&vb[(size_t)(k0 + kr) * DIM + d4]);
        }
        __syncthreads();

        #pragma unroll
        for (int kk = 0; kk < 32; kk++) {
            u64 v0 = *reinterpret_cast<const u64*>(&Vs[kk][tx * 4]);
            u64 v1 = *reinterpret_cast<const u64*>(&Vs[kk][tx * 4 + 2]);
            #pragma unroll
            for (int i = 0; i < 8; i++) {
                float pr = Pt[kk][ty * 8 + i];
                u64 pp = pack2(pr, pr);
                acc[i][0] = ffma2(pp, v0, acc[i][0]);
                acc[i][1] = ffma2(pp, v1, acc[i][1]);
            }
        }
        __syncthreads();
    }

    #pragma unroll
    for (int i = 0; i < 8; i++) {
        int q = q0 + ty * 8 + i;
        u64* orow = reinterpret_cast<u64*>(&O[(size_t)(b * SEQ + q) * DIM + h * HD]);
        orow[tx * 2]     = acc[i][0];
        orow[tx * 2 + 1] = acc[i][1];
    }
}

// ============================================================================
extern "C" void kernel_launch(void* const* d_in, const int* in_sizes, int n_in,
                              void* d_out, int out_size)
{
    int xi = 0;
    for (int i = 0; i < n_in; i++)
        if (in_sizes[i] == M_TOTAL * DIM) { xi = i; break; }
    const float* x = (const float*)d_in[xi];
    const float* Wm[4];
    int wn = 0;
    for (int i = 0; i < n_in && wn < 4; i++)
        if (i != xi) Wm[wn++] = (const float*)d_in[i];
    float* out = (float*)d_out;

    float *q, *k, *v, *attn, *s, *gc, *gs;
    __nv_bfloat16 *x3, *w3;
    cudaGetSymbolAddress((void**)&q,    g_q);
    cudaGetSymbolAddress((void**)&k,    g_k);
    cudaGetSymbolAddress((void**)&v,    g_v);
    cudaGetSymbolAddress((void**)&attn, g_attn);
    cudaGetSymbolAddress((void**)&s,    g_s);
    cudaGetSymbolAddress((void**)&gc,   g_cos);
    cudaGetSymbolAddress((void**)&gs,   g_sin);
    cudaGetSymbolAddress((void**)&x3,   g_x3);
    cudaGetSymbolAddress((void**)&w3,   g_w3);

    // splits: activations [hi|lo|hi], weights [hi|hi|lo]
    split_kernel<<<(M_TOTAL * DIM / 4 + 255) / 256, 256>>>(x, x3, M_TOTAL * DIM / 4,
                                                           2 * DIM, DIM);
    for (int i = 0; i < 4; i++)
        split_kernel<<<(DIM * DIM / 4 + 255) / 256, 256>>>(
            Wm[i], w3 + (size_t)i * DIM * K3, DIM * DIM / 4, DIM, 2 * DIM);

    // projections on HMMA tensor cores
    dim3 mgrid(DIM / 128, M_TOTAL / 128);     // (8, 64)
    hmma_gemm_kernel<<<mgrid, 256>>>(x3, w3,                       q);
    hmma_gemm_kernel<<<mgrid, 256>>>(x3, w3 + (size_t)1*DIM*K3,    k);
    hmma_gemm_kernel<<<mgrid, 256>>>(x3, w3 + (size_t)2*DIM*K3,    v);

    rope_table_kernel<<<SEQ * 32 / 256, 256>>>(gc, gs);
    rope_kernel<<<(M_TOTAL * NH * 32) / 256, 256>>>(q, k, gc, gs);

    qk_kernel<<<dim3(SEQ / 128, SEQ / 128, BATCH * NH), 256>>>(q, k, s);
    softmax_kernel<<<BATCH * NH * SEQ, 256>>>(s);
    pv_kernel<<<dim3(SEQ / 128, BATCH * NH), 256>>>(s, v, attn);

    // output projection
    split_kernel<<<(M_TOTAL * DIM / 4 + 255) / 256, 256>>>(attn, x3, M_TOTAL * DIM / 4,
                                                           2 * DIM, DIM);
    hmma_gemm_kernel<<<mgrid, 256>>>(x3, w3 + (size_t)3*DIM*K3, out);
}

// round 12
// speedup vs baseline: 8.8699x; 1.2858x over previous
#include <cuda_runtime.h>
#include <cuda_bf16.h>
#include <math.h>

#define BATCH 4
#define SEQ   2048
#define DIM   1024
#define NH    16
#define HD    64
#define M_TOTAL (BATCH*SEQ)
#define K3    (3*DIM)          // [Ah | Al | Ah] x [Bh | Bh | Bl]

typedef unsigned long long u64;
typedef unsigned int u32;

// ---------------- device scratch ----------------
__device__ float g_q[M_TOTAL*DIM];
__device__ float g_k[M_TOTAL*DIM];
__device__ float g_v[M_TOTAL*DIM];
__device__ float g_attn[M_TOTAL*DIM];
__device__ float g_s[(size_t)BATCH*NH*SEQ*SEQ];     // 1 GiB scores (bf16 P2 in place after softmax)
__device__ float g_cos[SEQ*32];
__device__ float g_sin[SEQ*32];
__device__ __nv_bfloat16 g_x3[(size_t)M_TOTAL*K3];  // [M][3072] = [hi | lo | hi]
__device__ __nv_bfloat16 g_w3[(size_t)4*DIM*K3];    // 4 x [1024][3072] = [hi | hi | lo]
__device__ __nv_bfloat16 g_q2[(size_t)BATCH*NH*SEQ*2*HD];  // [bh][l][qh(64)|ql(64)]
__device__ __nv_bfloat16 g_k2[(size_t)BATCH*NH*SEQ*2*HD];
__device__ __nv_bfloat16 g_vt[(size_t)BATCH*NH*HD*2*SEQ];  // [bh][d][vh(2048)|vl(2048)]

// ---------------- mma.sync helpers ----------------
__device__ __forceinline__ u32 smem_u32(const void* p) {
    u32 a;
    asm("{ .reg .u64 t; cvta.to.shared.u64 t, %1; cvt.u32.u64 %0, t; }" : "=r"(a) : "l"(p));
    return a;
}
__device__ __forceinline__ void ldsm_x4(u32& r0, u32& r1, u32& r2, u32& r3, u32 addr) {
    asm volatile("ldmatrix.sync.aligned.m8n8.x4.shared.b16 {%0,%1,%2,%3}, [%4];"
                 : "=r"(r0), "=r"(r1), "=r"(r2), "=r"(r3) : "r"(addr));
}
__device__ __forceinline__ void mma16816(float* c, const u32* a, u32 b0, u32 b1) {
    asm volatile(
        "mma.sync.aligned.m16n8k16.row.col.f32.bf16.bf16.f32 "
        "{%0,%1,%2,%3}, {%4,%5,%6,%7}, {%8,%9}, {%0,%1,%2,%3};"
        : "+f"(c[0]), "+f"(c[1]), "+f"(c[2]), "+f"(c[3])
        : "r"(a[0]), "r"(a[1]), "r"(a[2]), "r"(a[3]), "r"(b0), "r"(b1));
}
__device__ __forceinline__ void cpasync16(u32 dst, const void* src) {
    asm volatile("cp.async.cg.shared.global [%0], [%1], 16;" :: "r"(dst), "l"(src));
}
__device__ __forceinline__ void bf16_split4(float4 v, uint2& hv, uint2& lv) {
    __nv_bfloat16 h0 = __float2bfloat16(v.x);
    __nv_bfloat16 h1 = __float2bfloat16(v.y);
    __nv_bfloat16 h2 = __float2bfloat16(v.z);
    __nv_bfloat16 h3 = __float2bfloat16(v.w);
    __nv_bfloat16 l0 = __float2bfloat16(v.x - __bfloat162float(h0));
    __nv_bfloat16 l1 = __float2bfloat16(v.y - __bfloat162float(h1));
    __nv_bfloat16 l2 = __float2bfloat16(v.z - __bfloat162float(h2));
    __nv_bfloat16 l3 = __float2bfloat16(v.w - __bfloat162float(h3));
    __nv_bfloat162 hp[2] = {__nv_bfloat162(h0, h1), __nv_bfloat162(h2, h3)};
    __nv_bfloat162 lp[2] = {__nv_bfloat162(l0, l1), __nv_bfloat162(l2, l3)};
    hv = *reinterpret_cast<uint2*>(hp);
    lv = *reinterpret_cast<uint2*>(lp);
}

// ============================================================================
// Split fp32 -> bf16 three-segment row (pitch 3072) for projection GEMMs.
// ============================================================================
__global__ void split_kernel(const float* __restrict__ src,
                             __nv_bfloat16* __restrict__ dst, int n4,
                             int hi2_off, int lo_off)
{
    int i = blockIdx.x * blockDim.x + threadIdx.x;
    if (i >= n4) return;
    const int cols4 = DIM / 4;
    int r = i / cols4;
    int c = (i - r * cols4) * 4;
    uint2 hv, lv;
    bf16_split4(reinterpret_cast<const float4*>(src)[i], hv, lv);
    size_t base = (size_t)r * K3 + c;
    *reinterpret_cast<uint2*>(&dst[base])           = hv;
    *reinterpret_cast<uint2*>(&dst[base + hi2_off]) = hv;
    *reinterpret_cast<uint2*>(&dst[base + lo_off])  = lv;
}

// ============================================================================
// Split post-RoPE Q or K -> per-head bf16 [hi(64) | lo(64)] rows.
// ============================================================================
__global__ void split_qk_kernel(const float* __restrict__ src,
                                __nv_bfloat16* __restrict__ dst)
{
    int i = blockIdx.x * blockDim.x + threadIdx.x;   // over M_TOTAL*DIM/4
    int r = i >> 8;                                   // global row (b*SEQ+l)
    int c = (i & 255) << 2;                           // col in DIM
    int h = c >> 6, d = c & 63;
    int b = r >> 11, l = r & (SEQ - 1);
    uint2 hv, lv;
    bf16_split4(reinterpret_cast<const float4*>(src)[i], hv, lv);
    size_t base = ((size_t)((b * NH + h) * SEQ + l)) * (2 * HD) + d;
    *reinterpret_cast<uint2*>(&dst[base])      = hv;
    *reinterpret_cast<uint2*>(&dst[base + HD]) = lv;
}

// ============================================================================
// V -> transposed per-head bf16 [bh][d][ vh(2048) | vl(2048) ]
// ============================================================================
__global__ void vt_split_kernel(const float* __restrict__ V,
                                __nv_bfloat16* __restrict__ vt)
{
    __shared__ float tile[64][65];
    const int bh = blockIdx.y, b = bh >> 4, h = bh & 15;
    const int k0 = blockIdx.x * 64;
    const int tid = threadIdx.x;

    #pragma unroll
    for (int p = 0; p < 4; p++) {
        int idx = p * 256 + tid;          // 1024 float4 slots
        int kr  = idx >> 4;
        int c4  = (idx & 15) << 2;
        float4 v = *reinterpret_cast<const float4*>(
            &V[(size_t)(b * SEQ + k0 + kr) * DIM + h * HD + c4]);
        tile[kr][c4] = v.x; tile[kr][c4+1] = v.y; tile[kr][c4+2] = v.z; tile[kr][c4+3] = v.w;
    }
    __syncthreads();

    #pragma unroll
    for (int p = 0; p < 4; p++) {
        int idx = p * 256 + tid;          // 64 d x 16 k-groups
        int d   = idx >> 4;
        int k4  = (idx & 15) << 2;
        float4 v = make_float4(tile[k4][d], tile[k4+1][d], tile[k4+2][d], tile[k4+3][d]);
        uint2 hv, lv;
        bf16_split4(v, hv, lv);
        size_t base = ((size_t)(bh * HD + d)) * (2 * SEQ) + k0 + k4;
        *reinterpret_cast<uint2*>(&vt[base])       = hv;
        *reinterpret_cast<uint2*>(&vt[base + SEQ]) = lv;
    }
}

// ============================================================================
// HMMA bf16 GEMM: C[M,1024] = A3[M,3072] @ B3[1024,3072]^T  (projections)
// ============================================================================
#define PITCH 40
#define KB    32
#define STG_ELE (128*PITCH)

__global__ __launch_bounds__(256)
void hmma_gemm_kernel(const __nv_bfloat16* __restrict__ A3,
                      const __nv_bfloat16* __restrict__ B3,
                      float* __restrict__ C)
{
    __shared__ __nv_bfloat16 smA[2][STG_ELE];
    __shared__ __nv_bfloat16 smB[2][STG_ELE];

    const int tid  = threadIdx.x;
    const int wid  = tid >> 5;
    const int lane = tid & 31;
    const int wm   = wid & 1;
    const int wn   = wid >> 1;
    const int m0   = blockIdx.y * 128;
    const int n0   = blockIdx.x * 128;

    const u32 baseA = smem_u32(smA);
    const u32 baseB = smem_u32(smB);

    const __nv_bfloat16* Ag = A3 + (size_t)m0 * K3;
    const __nv_bfloat16* Bg = B3 + (size_t)n0 * K3;

    const int crow0 = (tid)       >> 2, cseg0 = (tid)       & 3;
    const int crow1 = (tid + 256) >> 2, cseg1 = (tid + 256) & 3;

    auto load_stage = [&](int st, int k0) {
        u32 dA = baseA + st * (STG_ELE * 2);
        u32 dB = baseB + st * (STG_ELE * 2);
        cpasync16(dA + (crow0 * PITCH + cseg0 * 8) * 2, &Ag[(size_t)crow0 * K3 + k0 + cseg0 * 8]);
        cpasync16(dA + (crow1 * PITCH + cseg1 * 8) * 2, &Ag[(size_t)crow1 * K3 + k0 + cseg1 * 8]);
        cpasync16(dB + (crow0 * PITCH + cseg0 * 8) * 2, &Bg[(size_t)crow0 * K3 + k0 + cseg0 * 8]);
        cpasync16(dB + (crow1 * PITCH + cseg1 * 8) * 2, &Bg[(size_t)crow1 * K3 + k0 + cseg1 * 8]);
    };

    float acc[4][4][4];
    #pragma unroll
    for (int i = 0; i < 4; i++)
        #pragma unroll
        for (int j = 0; j < 4; j++)
            #pragma unroll
            for (int e = 0; e < 4; e++) acc[i][j][e] = 0.f;

    const int mi = lane >> 3, mr = lane & 7;
    const int arow_off = (mi & 1) * 8 + mr;
    const int acol_off = (mi >> 1) * 8;
    const int brow_off = (mi >> 1) * 8 + mr;
    const int bcol_off = (mi & 1) * 8;

    load_stage(0, 0);
    asm volatile("cp.async.commit_group;");

    const int NIT = K3 / KB;   // 96
    for (int it = 0; it < NIT; it++) {
        if (it + 1 < NIT) load_stage((it + 1) & 1, (it + 1) * KB);
        asm volatile("cp.async.commit_group;");
        asm volatile("cp.async.wait_group 1;");
        __syncthreads();

        const int st = it & 1;
        const u32 sA = baseA + st * (STG_ELE * 2);
        const u32 sB = baseB + st * (STG_ELE * 2);

        #pragma unroll
        for (int ks = 0; ks < 2; ks++) {
            u32 a[4][4], b[2][4];
            #pragma unroll
            for (int tm = 0; tm < 4; tm++) {
                int row = wm * 64 + tm * 16 + arow_off;
                ldsm_x4(a[tm][0], a[tm][1], a[tm][2], a[tm][3],
                        sA + (row * PITCH + ks * 16 + acol_off) * 2);
            }
            #pragma unroll
            for (int tp = 0; tp < 2; tp++) {
                int row = wn * 32 + tp * 16 + brow_off;
                ldsm_x4(b[tp][0], b[tp][1], b[tp][2], b[tp][3],
                        sB + (row * PITCH + ks * 16 + bcol_off) * 2);
            }
            #pragma unroll
            for (int tm = 0; tm < 4; tm++)
                #pragma unroll
                for (int tn = 0; tn < 4; tn++)
                    mma16816(acc[tm][tn], a[tm], b[tn >> 1][(tn & 1) * 2], b[tn >> 1][(tn & 1) * 2 + 1]);
        }
        __syncthreads();
    }

    const int gid = lane >> 2, tig = lane & 3;
    #pragma unroll
    for (int tm = 0; tm < 4; tm++) {
        #pragma unroll
        for (int tn = 0; tn < 4; tn++) {
            int row = m0 + wm * 64 + tm * 16 + gid;
            int col = n0 + wn * 32 + tn * 8 + tig * 2;
            *reinterpret_cast<float2*>(&C[(size_t)row * DIM + col]) =
                make_float2(acc[tm][tn][0], acc[tm][tn][1]);
            *reinterpret_cast<float2*>(&C[(size_t)(row + 8) * DIM + col]) =
                make_float2(acc[tm][tn][2], acc[tm][tn][3]);
        }
    }
}

// ============================================================================
// QK via split HMMA: S[bh,q,k] = 0.125 * Q.K  (3 terms x K=64 -> 6 steps)
// ============================================================================
__global__ __launch_bounds__(256)
void qk_hmma_kernel(const __nv_bfloat16* __restrict__ Q2,
                    const __nv_bfloat16* __restrict__ K2,
                    float* __restrict__ S)
{
    __shared__ __nv_bfloat16 smA[2][STG_ELE];
    __shared__ __nv_bfloat16 smB[2][STG_ELE];

    const int tid  = threadIdx.x;
    const int wid  = tid >> 5;
    const int lane = tid & 31;
    const int wm   = wid & 1;
    const int wn   = wid >> 1;
    const int bh   = blockIdx.z;
    const int m0   = blockIdx.y * 128;
    const int n0   = blockIdx.x * 128;

    const u32 baseA = smem_u32(smA);
    const u32 baseB = smem_u32(smB);

    const __nv_bfloat16* Ag = Q2 + ((size_t)bh * SEQ + m0) * (2 * HD);
    const __nv_bfloat16* Bg = K2 + ((size_t)bh * SEQ + n0) * (2 * HD);

    const int crow0 = (tid)       >> 2, cseg0 = (tid)       & 3;
    const int crow1 = (tid + 256) >> 2, cseg1 = (tid + 256) & 3;

    auto load_stage = [&](int st, int ka, int kb) {
        u32 dA = baseA + st * (STG_ELE * 2);
        u32 dB = baseB + st * (STG_ELE * 2);
        cpasync16(dA + (crow0 * PITCH + cseg0 * 8) * 2, &Ag[(size_t)crow0 * (2*HD) + ka + cseg0 * 8]);
        cpasync16(dA + (crow1 * PITCH + cseg1 * 8) * 2, &Ag[(size_t)crow1 * (2*HD) + ka + cseg1 * 8]);
        cpasync16(dB + (crow0 * PITCH + cseg0 * 8) * 2, &Bg[(size_t)crow0 * (2*HD) + kb + cseg0 * 8]);
        cpasync16(dB + (crow1 * PITCH + cseg1 * 8) * 2, &Bg[(size_t)crow1 * (2*HD) + kb + cseg1 * 8]);
    };

    // it -> (term, inner): aoff uses ql for term 1; boff uses kl for term 2
    auto ka_of = [](int it) { int t = it >> 1, in = it & 1; return ((t == 1) ? HD : 0) + in * KB; };
    auto kb_of = [](int it) { int t = it >> 1, in = it & 1; return ((t == 2) ? HD : 0) + in * KB; };

    float acc[4][4][4];
    #pragma unroll
    for (int i = 0; i < 4; i++)
        #pragma unroll
        for (int j = 0; j < 4; j++)
            #pragma unroll
            for (int e = 0; e < 4; e++) acc[i][j][e] = 0.f;

    const int mi = lane >> 3, mr = lane & 7;
    const int arow_off = (mi & 1) * 8 + mr;
    const int acol_off = (mi >> 1) * 8;
    const int brow_off = (mi >> 1) * 8 + mr;
    const int bcol_off = (mi & 1) * 8;

    load_stage(0, ka_of(0), kb_of(0));
    asm volatile("cp.async.commit_group;");

    const int NIT = 6;
    for (int it = 0; it < NIT; it++) {
        if (it + 1 < NIT) load_stage((it + 1) & 1, ka_of(it + 1), kb_of(it + 1));
        asm volatile("cp.async.commit_group;");
        asm volatile("cp.async.wait_group 1;");
        __syncthreads();

        const int st = it & 1;
        const u32 sA = baseA + st * (STG_ELE * 2);
        const u32 sB = baseB + st * (STG_ELE * 2);

        #pragma unroll
        for (int ks = 0; ks < 2; ks++) {
            u32 a[4][4], b[2][4];
            #pragma unroll
            for (int tm = 0; tm < 4; tm++) {
                int row = wm * 64 + tm * 16 + arow_off;
                ldsm_x4(a[tm][0], a[tm][1], a[tm][2], a[tm][3],
                        sA + (row * PITCH + ks * 16 + acol_off) * 2);
            }
            #pragma unroll
            for (int tp = 0; tp < 2; tp++) {
                int row = wn * 32 + tp * 16 + brow_off;
                ldsm_x4(b[tp][0], b[tp][1], b[tp][2], b[tp][3],
                        sB + (row * PITCH + ks * 16 + bcol_off) * 2);
            }
            #pragma unroll
            for (int tm = 0; tm < 4; tm++)
                #pragma unroll
                for (int tn = 0; tn < 4; tn++)
                    mma16816(acc[tm][tn], a[tm], b[tn >> 1][(tn & 1) * 2], b[tn >> 1][(tn & 1) * 2 + 1]);
        }
        __syncthreads();
    }

    const int gid = lane >> 2, tig = lane & 3;
    #pragma unroll
    for (int tm = 0; tm < 4; tm++) {
        #pragma unroll
        for (int tn = 0; tn < 4; tn++) {
            int row = m0 + wm * 64 + tm * 16 + gid;
            int col = n0 + wn * 32 + tn * 8 + tig * 2;
            float* s0 = &S[((size_t)bh * SEQ + row) * SEQ + col];
            float* s1 = &S[((size_t)bh * SEQ + row + 8) * SEQ + col];
            *reinterpret_cast<float2*>(s0) =
                make_float2(acc[tm][tn][0] * 0.125f, acc[tm][tn][1] * 0.125f);
            *reinterpret_cast<float2*>(s1) =
                make_float2(acc[tm][tn][2] * 0.125f, acc[tm][tn][3] * 0.125f);
        }
    }
}

// ============================================================================
// Softmax: fp32 row in, bf16 [ph(2048)|pl(2048)] row out IN PLACE.
// Thread t owns contiguous cols t*8..t*8+7. All reads precede first barrier.
// ============================================================================
__global__ __launch_bounds__(256)
void softmax_kernel(float* __restrict__ S)
{
    __shared__ float red[8];
    float* p = S + (size_t)blockIdx.x * SEQ;
    const int t    = threadIdx.x;
    const int lane = t & 31;
    const int warp = t >> 5;

    float x[8];
    float4 v0 = *reinterpret_cast<float4*>(&p[t * 8]);
    float4 v1 = *reinterpret_cast<float4*>(&p[t * 8 + 4]);
    x[0]=v0.x; x[1]=v0.y; x[2]=v0.z; x[3]=v0.w;
    x[4]=v1.x; x[5]=v1.y; x[6]=v1.z; x[7]=v1.w;

    float mx = x[0];
    #pragma unroll
    for (int j = 1; j < 8; j++) mx = fmaxf(mx, x[j]);
    #pragma unroll
    for (int o = 16; o > 0; o >>= 1) mx = fmaxf(mx, __shfl_xor_sync(0xffffffffu, mx, o));
    if (lane == 0) red[warp] = mx;
    __syncthreads();
    mx = red[0];
    #pragma unroll
    for (int w = 1; w < 8; w++) mx = fmaxf(mx, red[w]);
    __syncthreads();

    float sum = 0.f;
    #pragma unroll
    for (int j = 0; j < 8; j++) { x[j] = __expf(x[j] - mx); sum += x[j]; }
    #pragma unroll
    for (int o = 16; o > 0; o >>= 1) sum += __shfl_xor_sync(0xffffffffu, sum, o);
    if (lane == 0) red[warp] = sum;
    __syncthreads();
    sum = red[0];
    #pragma unroll
    for (int w = 1; w < 8; w++) sum += red[w];

    float inv = 1.f / sum;
    __align__(16) __nv_bfloat16 hb[8], lb[8];
    #pragma unroll
    for (int j = 0; j < 8; j++) {
        float val = x[j] * inv;
        hb[j] = __float2bfloat16(val);
        lb[j] = __float2bfloat16(val - __bfloat162float(hb[j]));
    }
    __nv_bfloat16* row = reinterpret_cast<__nv_bfloat16*>(p);
    *reinterpret_cast<uint4*>(&row[t * 8])       = *reinterpret_cast<uint4*>(hb);
    *reinterpret_cast<uint4*>(&row[SEQ + t * 8]) = *reinterpret_cast<uint4*>(lb);
}

// ============================================================================
// PV via split HMMA: O[q,d] = sum_k P[q,k] V[k,d]. 128q x 64d tile,
// 3 terms x K=2048 -> 192 steps.
// ============================================================================
#define STG_B (64*PITCH)

__global__ __launch_bounds__(256)
void pv_hmma_kernel(const __nv_bfloat16* __restrict__ P2,
                    const __nv_bfloat16* __restrict__ VT,
                    float* __restrict__ O)
{
    __shared__ __nv_bfloat16 smA[2][STG_ELE];
    __shared__ __nv_bfloat16 smB[2][STG_B];

    const int tid  = threadIdx.x;
    const int wid  = tid >> 5;
    const int lane = tid & 31;
    const int wm   = wid & 3;          // 4 m-groups of 32 rows
    const int wn   = wid >> 2;         // 2 n-groups of 32 cols
    const int bh   = blockIdx.y, b = bh >> 4, h = bh & 15;
    const int q0   = blockIdx.x * 128;

    const u32 baseA = smem_u32(smA);
    const u32 baseB = smem_u32(smB);

    const __nv_bfloat16* Ag = P2 + ((size_t)bh * SEQ + q0) * (2 * SEQ);
    const __nv_bfloat16* Bg = VT + ((size_t)bh * HD) * (2 * SEQ);

    const int crow0 = (tid)       >> 2, cseg0 = (tid)       & 3;   // A: 2 chunks/thread
    const int crow1 = (tid + 256) >> 2, cseg1 = (tid + 256) & 3;
    const int brow  = tid >> 2,         bseg  = tid & 3;           // B: 1 chunk/thread

    auto load_stage = [&](int st, int ka, int kb) {
        u32 dA = baseA + st * (STG_ELE * 2);
        u32 dB = baseB + st * (STG_B * 2);
        cpasync16(dA + (crow0 * PITCH + cseg0 * 8) * 2, &Ag[(size_t)crow0 * (2*SEQ) + ka + cseg0 * 8]);
        cpasync16(dA + (crow1 * PITCH + cseg1 * 8) * 2, &Ag[(size_t)crow1 * (2*SEQ) + ka + cseg1 * 8]);
        cpasync16(dB + (brow  * PITCH + bseg  * 8) * 2, &Bg[(size_t)brow  * (2*SEQ) + kb + bseg  * 8]);
    };

    auto ka_of = [](int it) { int t = it >> 6, in = it & 63; return ((t == 1) ? SEQ : 0) + in * KB; };
    auto kb_of = [](int it) { int t = it >> 6, in = it & 63; return ((t == 2) ? SEQ : 0) + in * KB; };

    float acc[2][4][4];
    #pragma unroll
    for (int i = 0; i < 2; i++)
        #pragma unroll
        for (int j = 0; j < 4; j++)
            #pragma unroll
            for (int e = 0; e < 4; e++) acc[i][j][e] = 0.f;

    const int mi = lane >> 3, mr = lane & 7;
    const int arow_off = (mi & 1) * 8 + mr;
    const int acol_off = (mi >> 1) * 8;
    const int brow_off = (mi >> 1) * 8 + mr;
    const int bcol_off = (mi & 1) * 8;

    load_stage(0, ka_of(0), kb_of(0));
    asm volatile("cp.async.commit_group;");

    const int NIT = 192;
    for (int it = 0; it < NIT; it++) {
        if (it + 1 < NIT) load_stage((it + 1) & 1, ka_of(it + 1), kb_of(it + 1));
        asm volatile("cp.async.commit_group;");
        asm volatile("cp.async.wait_group 1;");
        __syncthreads();

        const int st = it & 1;
        const u32 sA = baseA + st * (STG_ELE * 2);
        const u32 sB = baseB + st * (STG_B * 2);

        #pragma unroll
        for (int ks = 0; ks < 2; ks++) {
            u32 a[2][4], b[2][4];
            #pragma unroll
            for (int tm = 0; tm < 2; tm++) {
                int row = wm * 32 + tm * 16 + arow_off;
                ldsm_x4(a[tm][0], a[tm][1], a[tm][2], a[tm][3],
                        sA + (row * PITCH + ks * 16 + acol_off) * 2);
            }
            #pragma unroll
            for (int tp = 0; tp < 2; tp++) {
                int row = wn * 32 + tp * 16 + brow_off;
                ldsm_x4(b[tp][0], b[tp][1], b[tp][2], b[tp][3],
                        sB + (row * PITCH + ks * 16 + bcol_off) * 2);
            }
            #pragma unroll
            for (int tm = 0; tm < 2; tm++)
                #pragma unroll
                for (int tn = 0; tn < 4; tn++)
                    mma16816(acc[tm][tn], a[tm], b[tn >> 1][(tn & 1) * 2], b[tn >> 1][(tn & 1) * 2 + 1]);
        }
        __syncthreads();
    }

    const int gid = lane >> 2, tig = lane & 3;
    #pragma unroll
    for (int tm = 0; tm < 2; tm++) {
        #pragma unroll
        for (int tn = 0; tn < 4; tn++) {
            int row = q0 + wm * 32 + tm * 16 + gid;
            int col = h * HD + wn * 32 + tn * 8 + tig * 2;
            *reinterpret_cast<float2*>(&O[(size_t)(b * SEQ + row) * DIM + col]) =
                make_float2(acc[tm][tn][0], acc[tm][tn][1]);
            *reinterpret_cast<float2*>(&O[(size_t)(b * SEQ + row + 8) * DIM + col]) =
                make_float2(acc[tm][tn][2], acc[tm][tn][3]);
        }
    }
}

// ============================================================================
// RoPE tables + RoPE (unchanged)
// ============================================================================
__global__ void rope_table_kernel(float* __restrict__ gc, float* __restrict__ gs)
{
    int idx = blockIdx.x * blockDim.x + threadIdx.x;
    int j = idx & 31;
    int l = idx >> 5;
    double inv = pow(10000.0, -(double)j / 32.0);
    double ang = (double)l * inv;
    gc[idx] = (float)cos(ang);
    gs[idx] = (float)sin(ang);
}

__global__ void rope_kernel(float* __restrict__ q, float* __restrict__ k,
                            const float* __restrict__ gc, const float* __restrict__ gs)
{
    int idx = blockIdx.x * blockDim.x + threadIdx.x;
    int j  = idx & 31;
    int h  = (idx >> 5) & (NH - 1);
    int ml = idx >> 9;
    int l  = ml & (SEQ - 1);

    float c = gc[l * 32 + j];
    float s = gs[l * 32 + j];

    size_t base = (size_t)ml * DIM + h * HD + j;
    float q1 = q[base], q2 = q[base + 32];
    q[base]      = q1 * c - q2 * s;
    q[base + 32] = q2 * c + q1 * s;
    float k1 = k[base], k2 = k[base + 32];
    k[base]      = k1 * c - k2 * s;
    k[base + 32] = k2 * c + k1 * s;
}

// ============================================================================
extern "C" void kernel_launch(void* const* d_in, const int* in_sizes, int n_in,
                              void* d_out, int out_size)
{
    int xi = 0;
    for (int i = 0; i < n_in; i++)
        if (in_sizes[i] == M_TOTAL * DIM) { xi = i; break; }
    const float* x = (const float*)d_in[xi];
    const float* Wm[4];
    int wn = 0;
    for (int i = 0; i < n_in && wn < 4; i++)
        if (i != xi) Wm[wn++] = (const float*)d_in[i];
    float* out = (float*)d_out;

    float *q, *k, *v, *attn, *s, *gc, *gs;
    __nv_bfloat16 *x3, *w3, *q2, *k2, *vt;
    cudaGetSymbolAddress((void**)&q,    g_q);
    cudaGetSymbolAddress((void**)&k,    g_k);
    cudaGetSymbolAddress((void**)&v,    g_v);
    cudaGetSymbolAddress((void**)&attn, g_attn);
    cudaGetSymbolAddress((void**)&s,    g_s);
    cudaGetSymbolAddress((void**)&gc,   g_cos);
    cudaGetSymbolAddress((void**)&gs,   g_sin);
    cudaGetSymbolAddress((void**)&x3,   g_x3);
    cudaGetSymbolAddress((void**)&w3,   g_w3);
    cudaGetSymbolAddress((void**)&q2,   g_q2);
    cudaGetSymbolAddress((void**)&k2,   g_k2);
    cudaGetSymbolAddress((void**)&vt,   g_vt);

    // splits: activations [hi|lo|hi], weights [hi|hi|lo]
    split_kernel<<<(M_TOTAL * DIM / 4 + 255) / 256, 256>>>(x, x3, M_TOTAL * DIM / 4,
                                                           2 * DIM, DIM);
    for (int i = 0; i < 4; i++)
        split_kernel<<<(DIM * DIM / 4 + 255) / 256, 256>>>(
            Wm[i], w3 + (size_t)i * DIM * K3, DIM * DIM / 4, DIM, 2 * DIM);

    // projections on HMMA tensor cores
    dim3 mgrid(DIM / 128, M_TOTAL / 128);     // (8, 64)
    hmma_gemm_kernel<<<mgrid, 256>>>(x3, w3,                       q);
    hmma_gemm_kernel<<<mgrid, 256>>>(x3, w3 + (size_t)1*DIM*K3,    k);
    hmma_gemm_kernel<<<mgrid, 256>>>(x3, w3 + (size_t)2*DIM*K3,    v);

    rope_table_kernel<<<SEQ * 32 / 256, 256>>>(gc, gs);
    rope_kernel<<<(M_TOTAL * NH * 32) / 256, 256>>>(q, k, gc, gs);

    // attention operand preparation
    split_qk_kernel<<<(M_TOTAL * DIM / 4) / 256, 256>>>(q, q2);
    split_qk_kernel<<<(M_TOTAL * DIM / 4) / 256, 256>>>(k, k2);
    vt_split_kernel<<<dim3(SEQ / 64, BATCH * NH), 256>>>(v, vt);

    // attention on HMMA tensor cores
    qk_hmma_kernel<<<dim3(SEQ / 128, SEQ / 128, BATCH * NH), 256>>>(q2, k2, s);
    softmax_kernel<<<BATCH * NH * SEQ, 256>>>(s);
    pv_hmma_kernel<<<dim3(SEQ / 128, BATCH * NH), 256>>>(
        (const __nv_bfloat16*)s, vt, attn);

    // output projection
    split_kernel<<<(M_TOTAL * DIM / 4 + 255) / 256, 256>>>(attn, x3, M_TOTAL * DIM / 4,
                                                           2 * DIM, DIM);
    hmma_gemm_kernel<<<mgrid, 256>>>(x3, w3 + (size_t)3*DIM*K3, out);
}

// round 15
// speedup vs baseline: 10.5991x; 1.1949x over previous
#include <cuda_runtime.h>
#include <cuda_bf16.h>
#include <math.h>

#define BATCH 4
#define SEQ   2048
#define DIM   1024
#define NH    16
#define HD    64
#define M_TOTAL (BATCH*SEQ)
#define K3    (3*DIM)          // [Ah | Al | Ah] x [Bh | Bh | Bl]

typedef unsigned long long u64;
typedef unsigned int u32;

// ---------------- device scratch ----------------
__device__ float g_q[M_TOTAL*DIM];
__device__ float g_k[M_TOTAL*DIM];
__device__ float g_v[M_TOTAL*DIM];
__device__ float g_attn[M_TOTAL*DIM];
__device__ float g_cos[SEQ*32];
__device__ float g_sin[SEQ*32];
__device__ __nv_bfloat16 g_x3[(size_t)M_TOTAL*K3];  // [M][3072] = [hi | lo | hi]
__device__ __nv_bfloat16 g_w3[(size_t)4*DIM*K3];    // 4 x [1024][3072] = [hi | hi | lo]
__device__ __nv_bfloat16 g_q2[(size_t)BATCH*NH*SEQ*2*HD];  // [bh][l][qh(64)|ql(64)]
__device__ __nv_bfloat16 g_k2[(size_t)BATCH*NH*SEQ*2*HD];
__device__ __nv_bfloat16 g_vt[(size_t)BATCH*NH*HD*2*SEQ];  // [bh][d][vh(2048)|vl(2048)]

// ---------------- mma.sync helpers ----------------
__device__ __forceinline__ u32 smem_u32(const void* p) {
    u32 a;
    asm("{ .reg .u64 t; cvta.to.shared.u64 t, %1; cvt.u32.u64 %0, t; }" : "=r"(a) : "l"(p));
    return a;
}
__device__ __forceinline__ void ldsm_x4(u32& r0, u32& r1, u32& r2, u32& r3, u32 addr) {
    asm volatile("ldmatrix.sync.aligned.m8n8.x4.shared.b16 {%0,%1,%2,%3}, [%4];"
                 : "=r"(r0), "=r"(r1), "=r"(r2), "=r"(r3) : "r"(addr));
}
__device__ __forceinline__ void mma16816(float* c, const u32* a, u32 b0, u32 b1) {
    asm volatile(
        "mma.sync.aligned.m16n8k16.row.col.f32.bf16.bf16.f32 "
        "{%0,%1,%2,%3}, {%4,%5,%6,%7}, {%8,%9}, {%0,%1,%2,%3};"
        : "+f"(c[0]), "+f"(c[1]), "+f"(c[2]), "+f"(c[3])
        : "r"(a[0]), "r"(a[1]), "r"(a[2]), "r"(a[3]), "r"(b0), "r"(b1));
}
__device__ __forceinline__ void cpasync16(u32 dst, const void* src) {
    asm volatile("cp.async.cg.shared.global [%0], [%1], 16;" :: "r"(dst), "l"(src));
}
__device__ __forceinline__ void bf16_split4(float4 v, uint2& hv, uint2& lv) {
    __nv_bfloat16 h0 = __float2bfloat16(v.x);
    __nv_bfloat16 h1 = __float2bfloat16(v.y);
    __nv_bfloat16 h2 = __float2bfloat16(v.z);
    __nv_bfloat16 h3 = __float2bfloat16(v.w);
    __nv_bfloat16 l0 = __float2bfloat16(v.x - __bfloat162float(h0));
    __nv_bfloat16 l1 = __float2bfloat16(v.y - __bfloat162float(h1));
    __nv_bfloat16 l2 = __float2bfloat16(v.z - __bfloat162float(h2));
    __nv_bfloat16 l3 = __float2bfloat16(v.w - __bfloat162float(h3));
    __nv_bfloat162 hp[2] = {__nv_bfloat162(h0, h1), __nv_bfloat162(h2, h3)};
    __nv_bfloat162 lp[2] = {__nv_bfloat162(l0, l1), __nv_bfloat162(l2, l3)};
    hv = *reinterpret_cast<uint2*>(hp);
    lv = *reinterpret_cast<uint2*>(lp);
}
__device__ __forceinline__ u32 bf162_of(float x, float y) {
    __nv_bfloat162 t(__float2bfloat16(x), __float2bfloat16(y));
    return *reinterpret_cast<u32*>(&t);
}

// ============================================================================
// Split fp32 -> bf16 three-segment row (pitch 3072) for projection GEMMs.
// ============================================================================
__global__ void split_kernel(const float* __restrict__ src,
                             __nv_bfloat16* __restrict__ dst, int n4,
                             int hi2_off, int lo_off)
{
    int i = blockIdx.x * blockDim.x + threadIdx.x;
    if (i >= n4) return;
    const int cols4 = DIM / 4;
    int r = i / cols4;
    int c = (i - r * cols4) * 4;
    uint2 hv, lv;
    bf16_split4(reinterpret_cast<const float4*>(src)[i], hv, lv);
    size_t base = (size_t)r * K3 + c;
    *reinterpret_cast<uint2*>(&dst[base])           = hv;
    *reinterpret_cast<uint2*>(&dst[base + hi2_off]) = hv;
    *reinterpret_cast<uint2*>(&dst[base + lo_off])  = lv;
}

// ============================================================================
// RoPE tables
// ============================================================================
__global__ void rope_table_kernel(float* __restrict__ gc, float* __restrict__ gs)
{
    int idx = blockIdx.x * blockDim.x + threadIdx.x;
    int j = idx & 31;
    int l = idx >> 5;
    double inv = pow(10000.0, -(double)j / 32.0);
    double ang = (double)l * inv;
    gc[idx] = (float)cos(ang);
    gs[idx] = (float)sin(ang);
}

// ============================================================================
// Fused RoPE + split: fp32 pre-RoPE Q or K -> per-head bf16 [hi(64)|lo(64)].
// ============================================================================
__global__ void rope_split_kernel(const float* __restrict__ src,
                                  __nv_bfloat16* __restrict__ dst,
                                  const float* __restrict__ gc,
                                  const float* __restrict__ gs)
{
    int i = blockIdx.x * blockDim.x + threadIdx.x;   // M_TOTAL*NH*8
    int jj = i & 7;                 // j0 = jj*4
    int h  = (i >> 3) & 15;
    int ml = i >> 7;
    int l  = ml & (SEQ - 1);
    int b  = ml >> 11;

    const float* base = src + (size_t)ml * DIM + h * HD;
    float4 x1 = *reinterpret_cast<const float4*>(base + jj * 4);
    float4 x2 = *reinterpret_cast<const float4*>(base + 32 + jj * 4);
    float4 c  = *reinterpret_cast<const float4*>(&gc[l * 32 + jj * 4]);
    float4 s  = *reinterpret_cast<const float4*>(&gs[l * 32 + jj * 4]);

    float4 o1 = make_float4(x1.x*c.x - x2.x*s.x, x1.y*c.y - x2.y*s.y,
                            x1.z*c.z - x2.z*s.z, x1.w*c.w - x2.w*s.w);
    float4 o2 = make_float4(x2.x*c.x + x1.x*s.x, x2.y*c.y + x1.y*s.y,
                            x2.z*c.z + x1.z*s.z, x2.w*c.w + x1.w*s.w);

    uint2 h1, l1, h2, l2;
    bf16_split4(o1, h1, l1);
    bf16_split4(o2, h2, l2);
    __nv_bfloat16* d = dst + ((size_t)((b * NH + h) * SEQ + l)) * (2 * HD);
    *reinterpret_cast<uint2*>(&d[jj * 4])           = h1;
    *reinterpret_cast<uint2*>(&d[32 + jj * 4])      = h2;
    *reinterpret_cast<uint2*>(&d[HD + jj * 4])      = l1;
    *reinterpret_cast<uint2*>(&d[HD + 32 + jj * 4]) = l2;
}

// ============================================================================
// V -> transposed per-head bf16 [bh][d][ vh(2048) | vl(2048) ]
// ============================================================================
__global__ void vt_split_kernel(const float* __restrict__ V,
                                __nv_bfloat16* __restrict__ vt)
{
    __shared__ float tile[64][65];
    const int bh = blockIdx.y, b = bh >> 4, h = bh & 15;
    const int k0 = blockIdx.x * 64;
    const int tid = threadIdx.x;

    #pragma unroll
    for (int p = 0; p < 4; p++) {
        int idx = p * 256 + tid;
        int kr  = idx >> 4;
        int c4  = (idx & 15) << 2;
        float4 v = *reinterpret_cast<const float4*>(
            &V[(size_t)(b * SEQ + k0 + kr) * DIM + h * HD + c4]);
        tile[kr][c4] = v.x; tile[kr][c4+1] = v.y; tile[kr][c4+2] = v.z; tile[kr][c4+3] = v.w;
    }
    __syncthreads();

    #pragma unroll
    for (int p = 0; p < 4; p++) {
        int idx = p * 256 + tid;
        int d   = idx >> 4;
        int k4  = (idx & 15) << 2;
        float4 v = make_float4(tile[k4][d], tile[k4+1][d], tile[k4+2][d], tile[k4+3][d]);
        uint2 hv, lv;
        bf16_split4(v, hv, lv);
        size_t base = ((size_t)(bh * HD + d)) * (2 * SEQ) + k0 + k4;
        *reinterpret_cast<uint2*>(&vt[base])       = hv;
        *reinterpret_cast<uint2*>(&vt[base + SEQ]) = lv;
    }
}

// ============================================================================
// HMMA bf16 GEMM: C[M,1024] = A3[M,3072] @ B3[1024,3072]^T  (projections)
// ============================================================================
#define PITCH 40
#define KB    32
#define STG_ELE (128*PITCH)

__global__ __launch_bounds__(256)
void hmma_gemm_kernel(const __nv_bfloat16* __restrict__ A3,
                      const __nv_bfloat16* __restrict__ B3,
                      float* __restrict__ C)
{
    __shared__ __nv_bfloat16 smA[2][STG_ELE];
    __shared__ __nv_bfloat16 smB[2][STG_ELE];

    const int tid  = threadIdx.x;
    const int wid  = tid >> 5;
    const int lane = tid & 31;
    const int wm   = wid & 1;
    const int wn   = wid >> 1;
    const int m0   = blockIdx.y * 128;
    const int n0   = blockIdx.x * 128;

    const u32 baseA = smem_u32(smA);
    const u32 baseB = smem_u32(smB);

    const __nv_bfloat16* Ag = A3 + (size_t)m0 * K3;
    const __nv_bfloat16* Bg = B3 + (size_t)n0 * K3;

    const int crow0 = (tid)       >> 2, cseg0 = (tid)       & 3;
    const int crow1 = (tid + 256) >> 2, cseg1 = (tid + 256) & 3;

    auto load_stage = [&](int st, int k0) {
        u32 dA = baseA + st * (STG_ELE * 2);
        u32 dB = baseB + st * (STG_ELE * 2);
        cpasync16(dA + (crow0 * PITCH + cseg0 * 8) * 2, &Ag[(size_t)crow0 * K3 + k0 + cseg0 * 8]);
        cpasync16(dA + (crow1 * PITCH + cseg1 * 8) * 2, &Ag[(size_t)crow1 * K3 + k0 + cseg1 * 8]);
        cpasync16(dB + (crow0 * PITCH + cseg0 * 8) * 2, &Bg[(size_t)crow0 * K3 + k0 + cseg0 * 8]);
        cpasync16(dB + (crow1 * PITCH + cseg1 * 8) * 2, &Bg[(size_t)crow1 * K3 + k0 + cseg1 * 8]);
    };

    float acc[4][4][4];
    #pragma unroll
    for (int i = 0; i < 4; i++)
        #pragma unroll
        for (int j = 0; j < 4; j++)
            #pragma unroll
            for (int e = 0; e < 4; e++) acc[i][j][e] = 0.f;

    const int mi = lane >> 3, mr = lane & 7;
    const int arow_off = (mi & 1) * 8 + mr;
    const int acol_off = (mi >> 1) * 8;
    const int brow_off = (mi >> 1) * 8 + mr;
    const int bcol_off = (mi & 1) * 8;

    load_stage(0, 0);
    asm volatile("cp.async.commit_group;");

    const int NIT = K3 / KB;   // 96
    for (int it = 0; it < NIT; it++) {
        if (it + 1 < NIT) load_stage((it + 1) & 1, (it + 1) * KB);
        asm volatile("cp.async.commit_group;");
        asm volatile("cp.async.wait_group 1;");
        __syncthreads();

        const int st = it & 1;
        const u32 sA = baseA + st * (STG_ELE * 2);
        const u32 sB = baseB + st * (STG_ELE * 2);

        #pragma unroll
        for (int ks = 0; ks < 2; ks++) {
            u32 a[4][4], b[2][4];
            #pragma unroll
            for (int tm = 0; tm < 4; tm++) {
                int row = wm * 64 + tm * 16 + arow_off;
                ldsm_x4(a[tm][0], a[tm][1], a[tm][2], a[tm][3],
                        sA + (row * PITCH + ks * 16 + acol_off) * 2);
            }
            #pragma unroll
            for (int tp = 0; tp < 2; tp++) {
                int row = wn * 32 + tp * 16 + brow_off;
                ldsm_x4(b[tp][0], b[tp][1], b[tp][2], b[tp][3],
                        sB + (row * PITCH + ks * 16 + bcol_off) * 2);
            }
            #pragma unroll
            for (int tm = 0; tm < 4; tm++)
                #pragma unroll
                for (int tn = 0; tn < 4; tn++)
                    mma16816(acc[tm][tn], a[tm], b[tn >> 1][(tn & 1) * 2], b[tn >> 1][(tn & 1) * 2 + 1]);
        }
        __syncthreads();
    }

    const int gid = lane >> 2, tig = lane & 3;
    #pragma unroll
    for (int tm = 0; tm < 4; tm++) {
        #pragma unroll
        for (int tn = 0; tn < 4; tn++) {
            int row = m0 + wm * 64 + tm * 16 + gid;
            int col = n0 + wn * 32 + tn * 8 + tig * 2;
            *reinterpret_cast<float2*>(&C[(size_t)row * DIM + col]) =
                make_float2(acc[tm][tn][0], acc[tm][tn][1]);
            *reinterpret_cast<float2*>(&C[(size_t)(row + 8) * DIM + col]) =
                make_float2(acc[tm][tn][2], acc[tm][tn][3]);
        }
    }
}

// ============================================================================
// Fused flash attention (HMMA): per block = (bh, 128-q tile).
// Q resident; loop over 16 k-tiles of 128: QK (3 terms x 64) -> online
// softmax (cross-warp reductions via smem) -> P bf16 hi/lo to smem ->
// PV (3 terms x 128) into persistent O accumulators.
// ============================================================================
#define SM_Q    0                    // 4 chunks x 128 x 40 x 2B = 40960
#define SM_K    40960                // 4 x 128 x 40 x 2      = 40960
#define SM_V    81920                // 8 x 64 x 40 x 2       = 40960
#define SM_P    122880               // 8 x 128 x 40 x 2      = 81920
#define SM_RED  204800               // 4 x 128 floats        = 2048
#define SM_RED2 206848               // 4 x 128 floats        = 2048
#define SM_ALPHA 208896              // 128 floats            = 512
#define SM_L    209408               // 128 floats            = 512
#define SM_TOTAL 209920
#define CHQ (128*PITCH)              // 5120 elements per 128-row chunk
#define CHV (64*PITCH)               // 2560 elements per 64-row chunk

__global__ __launch_bounds__(256)
void fused_attn_kernel(const __nv_bfloat16* __restrict__ Q2,
                       const __nv_bfloat16* __restrict__ K2t,
                       const __nv_bfloat16* __restrict__ VT,
                       float* __restrict__ O)
{
    extern __shared__ char sm[];
    const u32 sb = smem_u32(sm);
    float* redsm  = reinterpret_cast<float*>(sm + SM_RED);
    float* redsm2 = reinterpret_cast<float*>(sm + SM_RED2);
    float* alphasm= reinterpret_cast<float*>(sm + SM_ALPHA);
    float* lsm    = reinterpret_cast<float*>(sm + SM_L);

    const int tid  = threadIdx.x;
    const int wid  = tid >> 5;
    const int lane = tid & 31;
    const int gid  = lane >> 2, tig = lane & 3;
    // QK roles
    const int wm  = wid & 1;          // 64 q rows
    const int wn2 = wid >> 1;         // 32 k cols
    // PV roles
    const int wm3 = wid & 3;          // 32 q rows
    const int wn3 = wid >> 2;         // 32 d cols
    const int bh = blockIdx.y, b = bh >> 4, h = bh & 15;
    const int q0 = blockIdx.x * 128;

    const __nv_bfloat16* Qg = Q2 + ((size_t)bh * SEQ + q0) * (2 * HD);
    const __nv_bfloat16* Kg = K2t + ((size_t)bh * SEQ) * (2 * HD);
    const __nv_bfloat16* Vg = VT + (size_t)bh * HD * (2 * SEQ);

    const int mi_ = lane >> 3, mr = lane & 7;
    const int arow_off = (mi_ & 1) * 8 + mr;
    const int acol_off = (mi_ >> 1) * 8;
    const int brow_off = (mi_ >> 1) * 8 + mr;
    const int bcol_off = (mi_ & 1) * 8;

    // persistent state
    float m_i[4][2], l_i[4][2];
    #pragma unroll
    for (int tm = 0; tm < 4; tm++) { m_i[tm][0] = -1e30f; m_i[tm][1] = -1e30f;
                                     l_i[tm][0] = 0.f;    l_i[tm][1] = 0.f; }
    float o[2][4][4];
    #pragma unroll
    for (int tm = 0; tm < 2; tm++)
        #pragma unroll
        for (int tn = 0; tn < 4; tn++)
            #pragma unroll
            for (int e = 0; e < 4; e++) o[tm][tn][e] = 0.f;

    // load resident Q (2048 16B chunks)
    #pragma unroll
    for (int p = 0; p < 8; p++) {
        int idx = p * 256 + tid;
        int r = idx >> 4, s = idx & 15;
        cpasync16(sb + SM_Q + (((s >> 2) * CHQ) + r * PITCH + (s & 3) * 8) * 2,
                  &Qg[(size_t)r * (2 * HD) + s * 8]);
    }

    for (int t = 0; t < 16; t++) {
        // K tile (2048 chunks) + V tile (2048 chunks)
        #pragma unroll
        for (int p = 0; p < 8; p++) {
            int idx = p * 256 + tid;
            int r = idx >> 4, s = idx & 15;
            cpasync16(sb + SM_K + (((s >> 2) * CHQ) + r * PITCH + (s & 3) * 8) * 2,
                      &Kg[(size_t)(t * 128 + r) * (2 * HD) + s * 8]);
        }
        #pragma unroll
        for (int p = 0; p < 8; p++) {
            int idx = p * 256 + tid;
            int d = idx >> 5, s = idx & 31;
            int hi = (s < 16), c8 = s & 15;
            int chunk = (hi ? 0 : 4) + (c8 >> 2);
            cpasync16(sb + SM_V + (chunk * CHV + d * PITCH + (c8 & 3) * 8) * 2,
                      &Vg[(size_t)d * (2 * SEQ) + (hi ? 0 : SEQ) + t * 128 + c8 * 8]);
        }
        asm volatile("cp.async.commit_group;");
        asm volatile("cp.async.wait_group 0;");
        __syncthreads();

        // ---- QK: 3 terms x 64 -> 6 steps of K=32 ----
        float sacc[4][4][4];
        #pragma unroll
        for (int i = 0; i < 4; i++)
            #pragma unroll
            for (int j = 0; j < 4; j++)
                #pragma unroll
                for (int e = 0; e < 4; e++) sacc[i][j][e] = 0.f;

        #pragma unroll
        for (int step = 0; step < 6; step++) {
            int term = step >> 1, inner = step & 1;
            u32 sA = sb + SM_Q + (((term == 1 ? 2 : 0) + inner) * CHQ) * 2;
            u32 sB = sb + SM_K + (((term == 2 ? 2 : 0) + inner) * CHQ) * 2;
            #pragma unroll
            for (int ks = 0; ks < 2; ks++) {
                u32 a[4][4], bfr[2][4];
                #pragma unroll
                for (int tm = 0; tm < 4; tm++) {
                    int row = wm * 64 + tm * 16 + arow_off;
                    ldsm_x4(a[tm][0], a[tm][1], a[tm][2], a[tm][3],
                            sA + (row * PITCH + ks * 16 + acol_off) * 2);
                }
                #pragma unroll
                for (int tp = 0; tp < 2; tp++) {
                    int row = wn2 * 32 + tp * 16 + brow_off;
                    ldsm_x4(bfr[tp][0], bfr[tp][1], bfr[tp][2], bfr[tp][3],
                            sB + (row * PITCH + ks * 16 + bcol_off) * 2);
                }
                #pragma unroll
                for (int tm = 0; tm < 4; tm++)
                    #pragma unroll
                    for (int tn = 0; tn < 4; tn++)
                        mma16816(sacc[tm][tn], a[tm],
                                 bfr[tn >> 1][(tn & 1) * 2], bfr[tn >> 1][(tn & 1) * 2 + 1]);
            }
        }
        #pragma unroll
        for (int i = 0; i < 4; i++)
            #pragma unroll
            for (int j = 0; j < 4; j++)
                #pragma unroll
                for (int e = 0; e < 4; e++) sacc[i][j][e] *= 0.125f;

        // ---- row max: warp-local (over tig) then cross-warp via smem ----
        #pragma unroll
        for (int tm = 0; tm < 4; tm++)
            #pragma unroll
            for (int rh = 0; rh < 2; rh++) {
                float mx = sacc[tm][0][rh * 2];
                #pragma unroll
                for (int tn = 0; tn < 4; tn++) {
                    mx = fmaxf(mx, sacc[tm][tn][rh * 2]);
                    mx = fmaxf(mx, sacc[tm][tn][rh * 2 + 1]);
                }
                mx = fmaxf(mx, __shfl_xor_sync(0xffffffffu, mx, 1));
                mx = fmaxf(mx, __shfl_xor_sync(0xffffffffu, mx, 2));
                if (tig == 0)
                    redsm[wn2 * 128 + wm * 64 + tm * 16 + gid + rh * 8] = mx;
            }
        __syncthreads();

        // ---- m/alpha/P/rowsum ----
        float alpha_loc[4][2];
        #pragma unroll
        for (int tm = 0; tm < 4; tm++)
            #pragma unroll
            for (int rh = 0; rh < 2; rh++) {
                int row = wm * 64 + tm * 16 + gid + rh * 8;
                float tmax = fmaxf(fmaxf(redsm[row], redsm[128 + row]),
                                   fmaxf(redsm[256 + row], redsm[384 + row]));
                float mnew = fmaxf(m_i[tm][rh], tmax);
                float al = __expf(m_i[tm][rh] - mnew);
                m_i[tm][rh] = mnew;
                alpha_loc[tm][rh] = al;
                float rs = 0.f;
                #pragma unroll
                for (int tn = 0; tn < 4; tn++) {
                    float p0 = __expf(sacc[tm][tn][rh * 2]     - mnew);
                    float p1 = __expf(sacc[tm][tn][rh * 2 + 1] - mnew);
                    rs += p0 + p1;
                    int intra = tn * 8 + tig * 2;
                    *reinterpret_cast<u32*>(sm + SM_P + (wn2 * CHQ + row * PITCH + intra) * 2) =
                        bf162_of(p0, p1);
                    float h0f = __bfloat162float(__float2bfloat16(p0));
                    float h1f = __bfloat162float(__float2bfloat16(p1));
                    *reinterpret_cast<u32*>(sm + SM_P + ((4 + wn2) * CHQ + row * PITCH + intra) * 2) =
                        bf162_of(p0 - h0f, p1 - h1f);
                }
                rs += __shfl_xor_sync(0xffffffffu, rs, 1);
                rs += __shfl_xor_sync(0xffffffffu, rs, 2);
                if (tig == 0) redsm2[wn2 * 128 + row] = rs;
                if (wn2 == 0 && tig == 0) alphasm[row] = al;
            }
        __syncthreads();

        // ---- l update + O rescale ----
        #pragma unroll
        for (int tm = 0; tm < 4; tm++)
            #pragma unroll
            for (int rh = 0; rh < 2; rh++) {
                int row = wm * 64 + tm * 16 + gid + rh * 8;
                float tot = redsm2[row] + redsm2[128 + row] + redsm2[256 + row] + redsm2[384 + row];
                l_i[tm][rh] = alpha_loc[tm][rh] * l_i[tm][rh] + tot;
            }
        #pragma unroll
        for (int tm = 0; tm < 2; tm++)
            #pragma unroll
            for (int rh = 0; rh < 2; rh++) {
                float al = alphasm[wm3 * 32 + tm * 16 + gid + rh * 8];
                #pragma unroll
                for (int tn = 0; tn < 4; tn++) {
                    o[tm][tn][rh * 2]     *= al;
                    o[tm][tn][rh * 2 + 1] *= al;
                }
            }

        // ---- PV: 3 terms x 128 -> 12 steps of K=32 ----
        #pragma unroll
        for (int step = 0; step < 12; step++) {
            int term = step >> 2, inner = step & 3;
            u32 sA = sb + SM_P + (((term == 1 ? 4 : 0) + inner) * CHQ) * 2;
            u32 sB = sb + SM_V + (((term == 2 ? 4 : 0) + inner) * CHV) * 2;
            #pragma unroll
            for (int ks = 0; ks < 2; ks++) {
                u32 a[2][4], bfr[2][4];
                #pragma unroll
                for (int tm = 0; tm < 2; tm++) {
                    int row = wm3 * 32 + tm * 16 + arow_off;
                    ldsm_x4(a[tm][0], a[tm][1], a[tm][2], a[tm][3],
                            sA + (row * PITCH + ks * 16 + acol_off) * 2);
                }
                #pragma unroll
                for (int tp = 0; tp < 2; tp++) {
                    int row = wn3 * 32 + tp * 16 + brow_off;
                    ldsm_x4(bfr[tp][0], bfr[tp][1], bfr[tp][2], bfr[tp][3],
                            sB + (row * PITCH + ks * 16 + bcol_off) * 2);
                }
                #pragma unroll
                for (int tm = 0; tm < 2; tm++)
                    #pragma unroll
                    for (int tn = 0; tn < 4; tn++)
                        mma16816(o[tm][tn], a[tm],
                                 bfr[tn >> 1][(tn & 1) * 2], bfr[tn >> 1][(tn & 1) * 2 + 1]);
            }
        }
        __syncthreads();   // before next tile's loads overwrite K/V/P
    }

    // broadcast l, normalize, write out
    if (wn2 == 0 && tig == 0) {
        #pragma unroll
        for (int tm = 0; tm < 4; tm++)
            #pragma unroll
            for (int rh = 0; rh < 2; rh++)
                lsm[wm * 64 + tm * 16 + gid + rh * 8] = l_i[tm][rh];
    }
    __syncthreads();
    #pragma unroll
    for (int tm = 0; tm < 2; tm++) {
        int r0_ = wm3 * 32 + tm * 16 + gid;
        float inv0 = 1.f / lsm[r0_];
        float inv1 = 1.f / lsm[r0_ + 8];
        #pragma unroll
        for (int tn = 0; tn < 4; tn++) {
            int col = h * HD + wn3 * 32 + tn * 8 + tig * 2;
            *reinterpret_cast<float2*>(&O[(size_t)(b * SEQ + q0 + r0_) * DIM + col]) =
                make_float2(o[tm][tn][0] * inv0, o[tm][tn][1] * inv0);
            *reinterpret_cast<float2*>(&O[(size_t)(b * SEQ + q0 + r0_ + 8) * DIM + col]) =
                make_float2(o[tm][tn][2] * inv1, o[tm][tn][3] * inv1);
        }
    }
}

// ============================================================================
extern "C" void kernel_launch(void* const* d_in, const int* in_sizes, int n_in,
                              void* d_out, int out_size)
{
    int xi = 0;
    for (int i = 0; i < n_in; i++)
        if (in_sizes[i] == M_TOTAL * DIM) { xi = i; break; }
    const float* x = (const float*)d_in[xi];
    const float* Wm[4];
    int wn = 0;
    for (int i = 0; i < n_in && wn < 4; i++)
        if (i != xi) Wm[wn++] = (const float*)d_in[i];
    float* out = (float*)d_out;

    float *q, *k, *v, *attn, *gc, *gs;
    __nv_bfloat16 *x3, *w3, *q2, *k2, *vt;
    cudaGetSymbolAddress((void**)&q,    g_q);
    cudaGetSymbolAddress((void**)&k,    g_k);
    cudaGetSymbolAddress((void**)&v,    g_v);
    cudaGetSymbolAddress((void**)&attn, g_attn);
    cudaGetSymbolAddress((void**)&gc,   g_cos);
    cudaGetSymbolAddress((void**)&gs,   g_sin);
    cudaGetSymbolAddress((void**)&x3,   g_x3);
    cudaGetSymbolAddress((void**)&w3,   g_w3);
    cudaGetSymbolAddress((void**)&q2,   g_q2);
    cudaGetSymbolAddress((void**)&k2,   g_k2);
    cudaGetSymbolAddress((void**)&vt,   g_vt);

    cudaFuncSetAttribute(fused_attn_kernel,
                         cudaFuncAttributeMaxDynamicSharedMemorySize, SM_TOTAL);

    // splits: activations [hi|lo|hi], weights [hi|hi|lo]
    split_kernel<<<(M_TOTAL * DIM / 4 + 255) / 256, 256>>>(x, x3, M_TOTAL * DIM / 4,
                                                           2 * DIM, DIM);
    for (int i = 0; i < 4; i++)
        split_kernel<<<(DIM * DIM / 4 + 255) / 256, 256>>>(
            Wm[i], w3 + (size_t)i * DIM * K3, DIM * DIM / 4, DIM, 2 * DIM);

    // projections on HMMA tensor cores
    dim3 mgrid(DIM / 128, M_TOTAL / 128);     // (8, 64)
    hmma_gemm_kernel<<<mgrid, 256>>>(x3, w3,                       q);
    hmma_gemm_kernel<<<mgrid, 256>>>(x3, w3 + (size_t)1*DIM*K3,    k);
    hmma_gemm_kernel<<<mgrid, 256>>>(x3, w3 + (size_t)2*DIM*K3,    v);

    rope_table_kernel<<<SEQ * 32 / 256, 256>>>(gc, gs);

    // fused rope + split for Q,K; V transpose+split
    rope_split_kernel<<<(M_TOTAL * NH * 8) / 256, 256>>>(q, q2, gc, gs);
    rope_split_kernel<<<(M_TOTAL * NH * 8) / 256, 256>>>(k, k2, gc, gs);
    vt_split_kernel<<<dim3(SEQ / 64, BATCH * NH), 256>>>(v, vt);

    // fused flash attention
    fused_attn_kernel<<<dim3(SEQ / 128, BATCH * NH), 256, SM_TOTAL>>>(q2, k2, vt, attn);

    // output projection
    split_kernel<<<(M_TOTAL * DIM / 4 + 255) / 256, 256>>>(attn, x3, M_TOTAL * DIM / 4,
                                                           2 * DIM, DIM);
    hmma_gemm_kernel<<<mgrid, 256>>>(x3, w3 + (size_t)3*DIM*K3, out);
}

// round 16
// speedup vs baseline: 15.6543x; 1.4769x over previous
#include <cuda_runtime.h>
#include <cuda_bf16.h>
#include <cuda_fp16.h>
#include <math.h>

#define BATCH 4
#define SEQ   2048
#define DIM   1024
#define NH    16
#define HD    64
#define M_TOTAL (BATCH*SEQ)

typedef unsigned long long u64;
typedef unsigned int u32;

// ---------------- device scratch ----------------
__device__ float g_q[M_TOTAL*DIM];
__device__ float g_k[M_TOTAL*DIM];
__device__ float g_v[M_TOTAL*DIM];
__device__ float g_attn[M_TOTAL*DIM];
__device__ float g_cos[SEQ*32];
__device__ float g_sin[SEQ*32];
__device__ __half g_xf[(size_t)M_TOTAL*DIM];        // fp16 activations (x, later attn)
__device__ __half g_wf[(size_t)4*DIM*DIM];          // fp16 weights (Wq,Wk,Wv,Wo)
__device__ __nv_bfloat16 g_q2[(size_t)BATCH*NH*SEQ*2*HD];  // [bh][l][qh(64)|ql(64)]
__device__ __nv_bfloat16 g_k2[(size_t)BATCH*NH*SEQ*2*HD];
__device__ __nv_bfloat16 g_vt[(size_t)BATCH*NH*HD*2*SEQ];  // [bh][d][vh(2048)|vl(2048)]

// ---------------- mma.sync helpers ----------------
__device__ __forceinline__ u32 smem_u32(const void* p) {
    u32 a;
    asm("{ .reg .u64 t; cvta.to.shared.u64 t, %1; cvt.u32.u64 %0, t; }" : "=r"(a) : "l"(p));
    return a;
}
__device__ __forceinline__ void ldsm_x4(u32& r0, u32& r1, u32& r2, u32& r3, u32 addr) {
    asm volatile("ldmatrix.sync.aligned.m8n8.x4.shared.b16 {%0,%1,%2,%3}, [%4];"
                 : "=r"(r0), "=r"(r1), "=r"(r2), "=r"(r3) : "r"(addr));
}
__device__ __forceinline__ void mma16816(float* c, const u32* a, u32 b0, u32 b1) {
    asm volatile(
        "mma.sync.aligned.m16n8k16.row.col.f32.bf16.bf16.f32 "
        "{%0,%1,%2,%3}, {%4,%5,%6,%7}, {%8,%9}, {%0,%1,%2,%3};"
        : "+f"(c[0]), "+f"(c[1]), "+f"(c[2]), "+f"(c[3])
        : "r"(a[0]), "r"(a[1]), "r"(a[2]), "r"(a[3]), "r"(b0), "r"(b1));
}
__device__ __forceinline__ void mma16816h(float* c, const u32* a, u32 b0, u32 b1) {
    asm volatile(
        "mma.sync.aligned.m16n8k16.row.col.f32.f16.f16.f32 "
        "{%0,%1,%2,%3}, {%4,%5,%6,%7}, {%8,%9}, {%0,%1,%2,%3};"
        : "+f"(c[0]), "+f"(c[1]), "+f"(c[2]), "+f"(c[3])
        : "r"(a[0]), "r"(a[1]), "r"(a[2]), "r"(a[3]), "r"(b0), "r"(b1));
}
__device__ __forceinline__ void cpasync16(u32 dst, const void* src) {
    asm volatile("cp.async.cg.shared.global [%0], [%1], 16;" :: "r"(dst), "l"(src));
}
__device__ __forceinline__ void bf16_split4(float4 v, uint2& hv, uint2& lv) {
    __nv_bfloat16 h0 = __float2bfloat16(v.x);
    __nv_bfloat16 h1 = __float2bfloat16(v.y);
    __nv_bfloat16 h2 = __float2bfloat16(v.z);
    __nv_bfloat16 h3 = __float2bfloat16(v.w);
    __nv_bfloat16 l0 = __float2bfloat16(v.x - __bfloat162float(h0));
    __nv_bfloat16 l1 = __float2bfloat16(v.y - __bfloat162float(h1));
    __nv_bfloat16 l2 = __float2bfloat16(v.z - __bfloat162float(h2));
    __nv_bfloat16 l3 = __float2bfloat16(v.w - __bfloat162float(h3));
    __nv_bfloat162 hp[2] = {__nv_bfloat162(h0, h1), __nv_bfloat162(h2, h3)};
    __nv_bfloat162 lp[2] = {__nv_bfloat162(l0, l1), __nv_bfloat162(l2, l3)};
    hv = *reinterpret_cast<uint2*>(hp);
    lv = *reinterpret_cast<uint2*>(lp);
}
__device__ __forceinline__ u32 bf162_of(float x, float y) {
    __nv_bfloat162 t(__float2bfloat16(x), __float2bfloat16(y));
    return *reinterpret_cast<u32*>(&t);
}

// ============================================================================
// fp32 -> fp16 convert (vectorized)
// ============================================================================
__global__ void to_half_kernel(const float* __restrict__ src,
                               __half* __restrict__ dst, int n4)
{
    int i = blockIdx.x * blockDim.x + threadIdx.x;
    if (i >= n4) return;
    float4 v = reinterpret_cast<const float4*>(src)[i];
    __half2 h01 = __floats2half2_rn(v.x, v.y);
    __half2 h23 = __floats2half2_rn(v.z, v.w);
    uint2 out;
    out.x = *reinterpret_cast<u32*>(&h01);
    out.y = *reinterpret_cast<u32*>(&h23);
    reinterpret_cast<uint2*>(dst)[i] = out;
}

// ============================================================================
// RoPE tables
// ============================================================================
__global__ void rope_table_kernel(float* __restrict__ gc, float* __restrict__ gs)
{
    int idx = blockIdx.x * blockDim.x + threadIdx.x;
    int j = idx & 31;
    int l = idx >> 5;
    double inv = pow(10000.0, -(double)j / 32.0);
    double ang = (double)l * inv;
    gc[idx] = (float)cos(ang);
    gs[idx] = (float)sin(ang);
}

// ============================================================================
// Fused RoPE + split: fp32 pre-RoPE Q or K -> per-head bf16 [hi(64)|lo(64)].
// ============================================================================
__global__ void rope_split_kernel(const float* __restrict__ src,
                                  __nv_bfloat16* __restrict__ dst,
                                  const float* __restrict__ gc,
                                  const float* __restrict__ gs)
{
    int i = blockIdx.x * blockDim.x + threadIdx.x;   // M_TOTAL*NH*8
    int jj = i & 7;                 // j0 = jj*4
    int h  = (i >> 3) & 15;
    int ml = i >> 7;
    int l  = ml & (SEQ - 1);
    int b  = ml >> 11;

    const float* base = src + (size_t)ml * DIM + h * HD;
    float4 x1 = *reinterpret_cast<const float4*>(base + jj * 4);
    float4 x2 = *reinterpret_cast<const float4*>(base + 32 + jj * 4);
    float4 c  = *reinterpret_cast<const float4*>(&gc[l * 32 + jj * 4]);
    float4 s  = *reinterpret_cast<const float4*>(&gs[l * 32 + jj * 4]);

    float4 o1 = make_float4(x1.x*c.x - x2.x*s.x, x1.y*c.y - x2.y*s.y,
                            x1.z*c.z - x2.z*s.z, x1.w*c.w - x2.w*s.w);
    float4 o2 = make_float4(x2.x*c.x + x1.x*s.x, x2.y*c.y + x1.y*s.y,
                            x2.z*c.z + x1.z*s.z, x2.w*c.w + x1.w*s.w);

    uint2 h1, l1, h2, l2;
    bf16_split4(o1, h1, l1);
    bf16_split4(o2, h2, l2);
    __nv_bfloat16* d = dst + ((size_t)((b * NH + h) * SEQ + l)) * (2 * HD);
    *reinterpret_cast<uint2*>(&d[jj * 4])           = h1;
    *reinterpret_cast<uint2*>(&d[32 + jj * 4])      = h2;
    *reinterpret_cast<uint2*>(&d[HD + jj * 4])      = l1;
    *reinterpret_cast<uint2*>(&d[HD + 32 + jj * 4]) = l2;
}

// ============================================================================
// V -> transposed per-head bf16 [bh][d][ vh(2048) | vl(2048) ]
// ============================================================================
__global__ void vt_split_kernel(const float* __restrict__ V,
                                __nv_bfloat16* __restrict__ vt)
{
    __shared__ float tile[64][65];
    const int bh = blockIdx.y, b = bh >> 4, h = bh & 15;
    const int k0 = blockIdx.x * 64;
    const int tid = threadIdx.x;

    #pragma unroll
    for (int p = 0; p < 4; p++) {
        int idx = p * 256 + tid;
        int kr  = idx >> 4;
        int c4  = (idx & 15) << 2;
        float4 v = *reinterpret_cast<const float4*>(
            &V[(size_t)(b * SEQ + k0 + kr) * DIM + h * HD + c4]);
        tile[kr][c4] = v.x; tile[kr][c4+1] = v.y; tile[kr][c4+2] = v.z; tile[kr][c4+3] = v.w;
    }
    __syncthreads();

    #pragma unroll
    for (int p = 0; p < 4; p++) {
        int idx = p * 256 + tid;
        int d   = idx >> 4;
        int k4  = (idx & 15) << 2;
        float4 v = make_float4(tile[k4][d], tile[k4+1][d], tile[k4+2][d], tile[k4+3][d]);
        uint2 hv, lv;
        bf16_split4(v, hv, lv);
        size_t base = ((size_t)(bh * HD + d)) * (2 * SEQ) + k0 + k4;
        *reinterpret_cast<uint2*>(&vt[base])       = hv;
        *reinterpret_cast<uint2*>(&vt[base + SEQ]) = lv;
    }
}

// ============================================================================
// fp16 HMMA GEMM: C[M,1024] = A[M,1024] @ W[1024,1024]^T  (single fp16, K=1024)
// grid.z selects weight slice + output buffer (QKV batched; Wo separate).
// ============================================================================
#define PITCH 40
#define KB    32
#define STG_ELE (128*PITCH)
#define KDIM  DIM

__global__ __launch_bounds__(256)
void hmma_gemm_f16_kernel(const __half* __restrict__ A,
                          const __half* __restrict__ Wbase,
                          float* __restrict__ C0,
                          float* __restrict__ C1,
                          float* __restrict__ C2)
{
    __shared__ __half smA[2][STG_ELE];
    __shared__ __half smB[2][STG_ELE];

    const int tid  = threadIdx.x;
    const int wid  = tid >> 5;
    const int lane = tid & 31;
    const int wm   = wid & 1;
    const int wn   = wid >> 1;
    const int m0   = blockIdx.y * 128;
    const int n0   = blockIdx.x * 128;
    const int z    = blockIdx.z;

    float* C = (z == 0) ? C0 : (z == 1) ? C1 : C2;

    const u32 baseA = smem_u32(smA);
    const u32 baseB = smem_u32(smB);

    const __half* Ag = A + (size_t)m0 * KDIM;
    const __half* Bg = Wbase + (size_t)z * DIM * KDIM + (size_t)n0 * KDIM;

    const int crow0 = (tid)       >> 2, cseg0 = (tid)       & 3;
    const int crow1 = (tid + 256) >> 2, cseg1 = (tid + 256) & 3;

    auto load_stage = [&](int st, int k0) {
        u32 dA = baseA + st * (STG_ELE * 2);
        u32 dB = baseB + st * (STG_ELE * 2);
        cpasync16(dA + (crow0 * PITCH + cseg0 * 8) * 2, &Ag[(size_t)crow0 * KDIM + k0 + cseg0 * 8]);
        cpasync16(dA + (crow1 * PITCH + cseg1 * 8) * 2, &Ag[(size_t)crow1 * KDIM + k0 + cseg1 * 8]);
        cpasync16(dB + (crow0 * PITCH + cseg0 * 8) * 2, &Bg[(size_t)crow0 * KDIM + k0 + cseg0 * 8]);
        cpasync16(dB + (crow1 * PITCH + cseg1 * 8) * 2, &Bg[(size_t)crow1 * KDIM + k0 + cseg1 * 8]);
    };

    float acc[4][4][4];
    #pragma unroll
    for (int i = 0; i < 4; i++)
        #pragma unroll
        for (int j = 0; j < 4; j++)
            #pragma unroll
            for (int e = 0; e < 4; e++) acc[i][j][e] = 0.f;

    const int mi = lane >> 3, mr = lane & 7;
    const int arow_off = (mi & 1) * 8 + mr;
    const int acol_off = (mi >> 1) * 8;
    const int brow_off = (mi >> 1) * 8 + mr;
    const int bcol_off = (mi & 1) * 8;

    load_stage(0, 0);
    asm volatile("cp.async.commit_group;");

    const int NIT = KDIM / KB;   // 32
    for (int it = 0; it < NIT; it++) {
        if (it + 1 < NIT) load_stage((it + 1) & 1, (it + 1) * KB);
        asm volatile("cp.async.commit_group;");
        asm volatile("cp.async.wait_group 1;");
        __syncthreads();

        const int st = it & 1;
        const u32 sA = baseA + st * (STG_ELE * 2);
        const u32 sB = baseB + st * (STG_ELE * 2);

        #pragma unroll
        for (int ks = 0; ks < 2; ks++) {
            u32 a[4][4], b[2][4];
            #pragma unroll
            for (int tm = 0; tm < 4; tm++) {
                int row = wm * 64 + tm * 16 + arow_off;
                ldsm_x4(a[tm][0], a[tm][1], a[tm][2], a[tm][3],
                        sA + (row * PITCH + ks * 16 + acol_off) * 2);
            }
            #pragma unroll
            for (int tp = 0; tp < 2; tp++) {
                int row = wn * 32 + tp * 16 + brow_off;
                ldsm_x4(b[tp][0], b[tp][1], b[tp][2], b[tp][3],
                        sB + (row * PITCH + ks * 16 + bcol_off) * 2);
            }
            #pragma unroll
            for (int tm = 0; tm < 4; tm++)
                #pragma unroll
                for (int tn = 0; tn < 4; tn++)
                    mma16816h(acc[tm][tn], a[tm], b[tn >> 1][(tn & 1) * 2], b[tn >> 1][(tn & 1) * 2 + 1]);
        }
        __syncthreads();
    }

    const int gid = lane >> 2, tig = lane & 3;
    #pragma unroll
    for (int tm = 0; tm < 4; tm++) {
        #pragma unroll
        for (int tn = 0; tn < 4; tn++) {
            int row = m0 + wm * 64 + tm * 16 + gid;
            int col = n0 + wn * 32 + tn * 8 + tig * 2;
            *reinterpret_cast<float2*>(&C[(size_t)row * DIM + col]) =
                make_float2(acc[tm][tn][0], acc[tm][tn][1]);
            *reinterpret_cast<float2*>(&C[(size_t)(row + 8) * DIM + col]) =
                make_float2(acc[tm][tn][2], acc[tm][tn][3]);
        }
    }
}

// ============================================================================
// Fused flash attention (HMMA bf16 3-term) — unchanged from R15 (passing).
// ============================================================================
#define SM_Q    0
#define SM_K    40960
#define SM_V    81920
#define SM_P    122880
#define SM_RED  204800
#define SM_RED2 206848
#define SM_ALPHA 208896
#define SM_L    209408
#define SM_TOTAL 209920
#define CHQ (128*PITCH)
#define CHV (64*PITCH)

__global__ __launch_bounds__(256)
void fused_attn_kernel(const __nv_bfloat16* __restrict__ Q2,
                       const __nv_bfloat16* __restrict__ K2t,
                       const __nv_bfloat16* __restrict__ VT,
                       float* __restrict__ O)
{
    extern __shared__ char sm[];
    const u32 sb = smem_u32(sm);
    float* redsm  = reinterpret_cast<float*>(sm + SM_RED);
    float* redsm2 = reinterpret_cast<float*>(sm + SM_RED2);
    float* alphasm= reinterpret_cast<float*>(sm + SM_ALPHA);
    float* lsm    = reinterpret_cast<float*>(sm + SM_L);

    const int tid  = threadIdx.x;
    const int wid  = tid >> 5;
    const int lane = tid & 31;
    const int gid  = lane >> 2, tig = lane & 3;
    const int wm  = wid & 1;
    const int wn2 = wid >> 1;
    const int wm3 = wid & 3;
    const int wn3 = wid >> 2;
    const int bh = blockIdx.y, b = bh >> 4, h = bh & 15;
    const int q0 = blockIdx.x * 128;

    const __nv_bfloat16* Qg = Q2 + ((size_t)bh * SEQ + q0) * (2 * HD);
    const __nv_bfloat16* Kg = K2t + ((size_t)bh * SEQ) * (2 * HD);
    const __nv_bfloat16* Vg = VT + (size_t)bh * HD * (2 * SEQ);

    const int mi_ = lane >> 3, mr = lane & 7;
    const int arow_off = (mi_ & 1) * 8 + mr;
    const int acol_off = (mi_ >> 1) * 8;
    const int brow_off = (mi_ >> 1) * 8 + mr;
    const int bcol_off = (mi_ & 1) * 8;

    float m_i[4][2], l_i[4][2];
    #pragma unroll
    for (int tm = 0; tm < 4; tm++) { m_i[tm][0] = -1e30f; m_i[tm][1] = -1e30f;
                                     l_i[tm][0] = 0.f;    l_i[tm][1] = 0.f; }
    float o[2][4][4];
    #pragma unroll
    for (int tm = 0; tm < 2; tm++)
        #pragma unroll
        for (int tn = 0; tn < 4; tn++)
            #pragma unroll
            for (int e = 0; e < 4; e++) o[tm][tn][e] = 0.f;

    #pragma unroll
    for (int p = 0; p < 8; p++) {
        int idx = p * 256 + tid;
        int r = idx >> 4, s = idx & 15;
        cpasync16(sb + SM_Q + (((s >> 2) * CHQ) + r * PITCH + (s & 3) * 8) * 2,
                  &Qg[(size_t)r * (2 * HD) + s * 8]);
    }

    for (int t = 0; t < 16; t++) {
        #pragma unroll
        for (int p = 0; p < 8; p++) {
            int idx = p * 256 + tid;
            int r = idx >> 4, s = idx & 15;
            cpasync16(sb + SM_K + (((s >> 2) * CHQ) + r * PITCH + (s & 3) * 8) * 2,
                      &Kg[(size_t)(t * 128 + r) * (2 * HD) + s * 8]);
        }
        #pragma unroll
        for (int p = 0; p < 8; p++) {
            int idx = p * 256 + tid;
            int d = idx >> 5, s = idx & 31;
            int hi = (s < 16), c8 = s & 15;
            int chunk = (hi ? 0 : 4) + (c8 >> 2);
            cpasync16(sb + SM_V + (chunk * CHV + d * PITCH + (c8 & 3) * 8) * 2,
                      &Vg[(size_t)d * (2 * SEQ) + (hi ? 0 : SEQ) + t * 128 + c8 * 8]);
        }
        asm volatile("cp.async.commit_group;");
        asm volatile("cp.async.wait_group 0;");
        __syncthreads();

        float sacc[4][4][4];
        #pragma unroll
        for (int i = 0; i < 4; i++)
            #pragma unroll
            for (int j = 0; j < 4; j++)
                #pragma unroll
                for (int e = 0; e < 4; e++) sacc[i][j][e] = 0.f;

        #pragma unroll
        for (int step = 0; step < 6; step++) {
            int term = step >> 1, inner = step & 1;
            u32 sA = sb + SM_Q + (((term == 1 ? 2 : 0) + inner) * CHQ) * 2;
            u32 sB = sb + SM_K + (((term == 2 ? 2 : 0) + inner) * CHQ) * 2;
            #pragma unroll
            for (int ks = 0; ks < 2; ks++) {
                u32 a[4][4], bfr[2][4];
                #pragma unroll
                for (int tm = 0; tm < 4; tm++) {
                    int row = wm * 64 + tm * 16 + arow_off;
                    ldsm_x4(a[tm][0], a[tm][1], a[tm][2], a[tm][3],
                            sA + (row * PITCH + ks * 16 + acol_off) * 2);
                }
                #pragma unroll
                for (int tp = 0; tp < 2; tp++) {
                    int row = wn2 * 32 + tp * 16 + brow_off;
                    ldsm_x4(bfr[tp][0], bfr[tp][1], bfr[tp][2], bfr[tp][3],
                            sB + (row * PITCH + ks * 16 + bcol_off) * 2);
                }
                #pragma unroll
                for (int tm = 0; tm < 4; tm++)
                    #pragma unroll
                    for (int tn = 0; tn < 4; tn++)
                        mma16816(sacc[tm][tn], a[tm],
                                 bfr[tn >> 1][(tn & 1) * 2], bfr[tn >> 1][(tn & 1) * 2 + 1]);
            }
        }
        #pragma unroll
        for (int i = 0; i < 4; i++)
            #pragma unroll
            for (int j = 0; j < 4; j++)
                #pragma unroll
                for (int e = 0; e < 4; e++) sacc[i][j][e] *= 0.125f;

        #pragma unroll
        for (int tm = 0; tm < 4; tm++)
            #pragma unroll
            for (int rh = 0; rh < 2; rh++) {
                float mx = sacc[tm][0][rh * 2];
                #pragma unroll
                for (int tn = 0; tn < 4; tn++) {
                    mx = fmaxf(mx, sacc[tm][tn][rh * 2]);
                    mx = fmaxf(mx, sacc[tm][tn][rh * 2 + 1]);
                }
                mx = fmaxf(mx, __shfl_xor_sync(0xffffffffu, mx, 1));
                mx = fmaxf(mx, __shfl_xor_sync(0xffffffffu, mx, 2));
                if (tig == 0)
                    redsm[wn2 * 128 + wm * 64 + tm * 16 + gid + rh * 8] = mx;
            }
        __syncthreads();

        float alpha_loc[4][2];
        #pragma unroll
        for (int tm = 0; tm < 4; tm++)
            #pragma unroll
            for (int rh = 0; rh < 2; rh++) {
                int row = wm * 64 + tm * 16 + gid + rh * 8;
                float tmax = fmaxf(fmaxf(redsm[row], redsm[128 + row]),
                                   fmaxf(redsm[256 + row], redsm[384 + row]));
                float mnew = fmaxf(m_i[tm][rh], tmax);
                float al = __expf(m_i[tm][rh] - mnew);
                m_i[tm][rh] = mnew;
                alpha_loc[tm][rh] = al;
                float rs = 0.f;
                #pragma unroll
                for (int tn = 0; tn < 4; tn++) {
                    float p0 = __expf(sacc[tm][tn][rh * 2]     - mnew);
                    float p1 = __expf(sacc[tm][tn][rh * 2 + 1] - mnew);
                    rs += p0 + p1;
                    int intra = tn * 8 + tig * 2;
                    *reinterpret_cast<u32*>(sm + SM_P + (wn2 * CHQ + row * PITCH + intra) * 2) =
                        bf162_of(p0, p1);
                    float h0f = __bfloat162float(__float2bfloat16(p0));
                    float h1f = __bfloat162float(__float2bfloat16(p1));
                    *reinterpret_cast<u32*>(sm + SM_P + ((4 + wn2) * CHQ + row * PITCH + intra) * 2) =
                        bf162_of(p0 - h0f, p1 - h1f);
                }
                rs += __shfl_xor_sync(0xffffffffu, rs, 1);
                rs += __shfl_xor_sync(0xffffffffu, rs, 2);
                if (tig == 0) redsm2[wn2 * 128 + row] = rs;
                if (wn2 == 0 && tig == 0) alphasm[row] = al;
            }
        __syncthreads();

        #pragma unroll
        for (int tm = 0; tm < 4; tm++)
            #pragma unroll
            for (int rh = 0; rh < 2; rh++) {
                int row = wm * 64 + tm * 16 + gid + rh * 8;
                float tot = redsm2[row] + redsm2[128 + row] + redsm2[256 + row] + redsm2[384 + row];
                l_i[tm][rh] = alpha_loc[tm][rh] * l_i[tm][rh] + tot;
            }
        #pragma unroll
        for (int tm = 0; tm < 2; tm++)
            #pragma unroll
            for (int rh = 0; rh < 2; rh++) {
                float al = alphasm[wm3 * 32 + tm * 16 + gid + rh * 8];
                #pragma unroll
                for (int tn = 0; tn < 4; tn++) {
                    o[tm][tn][rh * 2]     *= al;
                    o[tm][tn][rh * 2 + 1] *= al;
                }
            }

        #pragma unroll
        for (int step = 0; step < 12; step++) {
            int term = step >> 2, inner = step & 3;
            u32 sA = sb + SM_P + (((term == 1 ? 4 : 0) + inner) * CHQ) * 2;
            u32 sB = sb + SM_V + (((term == 2 ? 4 : 0) + inner) * CHV) * 2;
            #pragma unroll
            for (int ks = 0; ks < 2; ks++) {
                u32 a[2][4], bfr[2][4];
                #pragma unroll
                for (int tm = 0; tm < 2; tm++) {
                    int row = wm3 * 32 + tm * 16 + arow_off;
                    ldsm_x4(a[tm][0], a[tm][1], a[tm][2], a[tm][3],
                            sA + (row * PITCH + ks * 16 + acol_off) * 2);
                }
                #pragma unroll
                for (int tp = 0; tp < 2; tp++) {
                    int row = wn3 * 32 + tp * 16 + brow_off;
                    ldsm_x4(bfr[tp][0], bfr[tp][1], bfr[tp][2], bfr[tp][3],
                            sB + (row * PITCH + ks * 16 + bcol_off) * 2);
                }
                #pragma unroll
                for (int tm = 0; tm < 2; tm++)
                    #pragma unroll
                    for (int tn = 0; tn < 4; tn++)
                        mma16816(o[tm][tn], a[tm],
                                 bfr[tn >> 1][(tn & 1) * 2], bfr[tn >> 1][(tn & 1) * 2 + 1]);
            }
        }
        __syncthreads();
    }

    if (wn2 == 0 && tig == 0) {
        #pragma unroll
        for (int tm = 0; tm < 4; tm++)
            #pragma unroll
            for (int rh = 0; rh < 2; rh++)
                lsm[wm * 64 + tm * 16 + gid + rh * 8] = l_i[tm][rh];
    }
    __syncthreads();
    #pragma unroll
    for (int tm = 0; tm < 2; tm++) {
        int r0_ = wm3 * 32 + tm * 16 + gid;
        float inv0 = 1.f / lsm[r0_];
        float inv1 = 1.f / lsm[r0_ + 8];
        #pragma unroll
        for (int tn = 0; tn < 4; tn++) {
            int col = h * HD + wn3 * 32 + tn * 8 + tig * 2;
            *reinterpret_cast<float2*>(&O[(size_t)(b * SEQ + q0 + r0_) * DIM + col]) =
                make_float2(o[tm][tn][0] * inv0, o[tm][tn][1] * inv0);
            *reinterpret_cast<float2*>(&O[(size_t)(b * SEQ + q0 + r0_ + 8) * DIM + col]) =
                make_float2(o[tm][tn][2] * inv1, o[tm][tn][3] * inv1);
        }
    }
}

// ============================================================================
extern "C" void kernel_launch(void* const* d_in, const int* in_sizes, int n_in,
                              void* d_out, int out_size)
{
    int xi = 0;
    for (int i = 0; i < n_in; i++)
        if (in_sizes[i] == M_TOTAL * DIM) { xi = i; break; }
    const float* x = (const float*)d_in[xi];
    const float* Wm[4];
    int wn = 0;
    for (int i = 0; i < n_in && wn < 4; i++)
        if (i != xi) Wm[wn++] = (const float*)d_in[i];
    float* out = (float*)d_out;

    float *q, *k, *v, *attn, *gc, *gs;
    __half *xf, *wf;
    __nv_bfloat16 *q2, *k2, *vt;
    cudaGetSymbolAddress((void**)&q,    g_q);
    cudaGetSymbolAddress((void**)&k,    g_k);
    cudaGetSymbolAddress((void**)&v,    g_v);
    cudaGetSymbolAddress((void**)&attn, g_attn);
    cudaGetSymbolAddress((void**)&gc,   g_cos);
    cudaGetSymbolAddress((void**)&gs,   g_sin);
    cudaGetSymbolAddress((void**)&xf,   g_xf);
    cudaGetSymbolAddress((void**)&wf,   g_wf);
    cudaGetSymbolAddress((void**)&q2,   g_q2);
    cudaGetSymbolAddress((void**)&k2,   g_k2);
    cudaGetSymbolAddress((void**)&vt,   g_vt);

    cudaFuncSetAttribute(fused_attn_kernel,
                         cudaFuncAttributeMaxDynamicSharedMemorySize, SM_TOTAL);

    // fp16 converts: x + 4 weights
    to_half_kernel<<<(M_TOTAL * DIM / 4 + 255) / 256, 256>>>(x, xf, M_TOTAL * DIM / 4);
    for (int i = 0; i < 4; i++)
        to_half_kernel<<<(DIM * DIM / 4 + 255) / 256, 256>>>(
            Wm[i], wf + (size_t)i * DIM * DIM, DIM * DIM / 4);

    // QKV projections: one batched launch (grid.z = 3)
    dim3 mgrid(DIM / 128, M_TOTAL / 128, 3);     // (8, 64, 3)
    hmma_gemm_f16_kernel<<<mgrid, 256>>>(xf, wf, q, k, v);

    rope_table_kernel<<<SEQ * 32 / 256, 256>>>(gc, gs);

    // fused rope + split for Q,K; V transpose+split (bf16 hi/lo, unchanged)
    rope_split_kernel<<<(M_TOTAL * NH * 8) / 256, 256>>>(q, q2, gc, gs);
    rope_split_kernel<<<(M_TOTAL * NH * 8) / 256, 256>>>(k, k2, gc, gs);
    vt_split_kernel<<<dim3(SEQ / 64, BATCH * NH), 256>>>(v, vt);

    // fused flash attention (bf16 3-term, unchanged)
    fused_attn_kernel<<<dim3(SEQ / 128, BATCH * NH), 256, SM_TOTAL>>>(q2, k2, vt, attn);

    // output projection: convert attn to fp16, single GEMM with Wo
    to_half_kernel<<<(M_TOTAL * DIM / 4 + 255) / 256, 256>>>(attn, xf, M_TOTAL * DIM / 4);
    dim3 ogrid(DIM / 128, M_TOTAL / 128, 1);
    hmma_gemm_f16_kernel<<<ogrid, 256>>>(xf, wf + (size_t)3 * DIM * DIM, out, out, out);
}